// round 14
// baseline (speedup 1.0000x reference)
#include <cuda_runtime.h>
#include <cuda_bf16.h>
#include <math.h>
#include <stdint.h>

#define Bsz 16384
#define Hd  128
#define Cc  4
#define Ll  6
#define NHh 4
#define HDd 32
#define Oo  1024
#define G3H 384

// ---------------- fp32 scratch ----------------------------------------------
__device__ __align__(256) float g_msg[(size_t)Cc * Bsz * Hd];

// ---------------- bf16 hi/lo split buffers ----------------------------------
__device__ __align__(256) __nv_bfloat16 g_gih[(size_t)Cc * Bsz * G3H];   // gi split
__device__ __align__(256) __nv_bfloat16 g_gil[(size_t)Cc * Bsz * G3H];
__device__ __align__(256) __nv_bfloat16 g_ghh[(size_t)Cc * Bsz * G3H];   // gh split
__device__ __align__(256) __nv_bfloat16 g_ghl[(size_t)Cc * Bsz * G3H];
__device__ __align__(256) __nv_bfloat16 g_qkh[(size_t)Cc * Bsz * G3H];   // qkv split
__device__ __align__(256) __nv_bfloat16 g_qkl[(size_t)Cc * Bsz * G3H];
__device__ __align__(256) __nv_bfloat16 g_x0h[(size_t)Bsz * Hd];
__device__ __align__(256) __nv_bfloat16 g_x0l[(size_t)Bsz * Hd];
__device__ __align__(256) __nv_bfloat16 g_hh [(size_t)Ll * Cc * Bsz * Hd];  // h_in split
__device__ __align__(256) __nv_bfloat16 g_hl [(size_t)Ll * Cc * Bsz * Hd];
__device__ __align__(256) __nv_bfloat16 g_nh [(size_t)Cc * Bsz * Hd];       // hn split
__device__ __align__(256) __nv_bfloat16 g_nl [(size_t)Cc * Bsz * Hd];
__device__ __align__(256) __nv_bfloat16 g_aah[(size_t)Cc * Bsz * Hd];       // att split
__device__ __align__(256) __nv_bfloat16 g_aal[(size_t)Cc * Bsz * Hd];
__device__ __align__(256) __nv_bfloat16 g_ph [(size_t)Cc * Bsz * Hd];       // hOut split
__device__ __align__(256) __nv_bfloat16 g_pl [(size_t)Cc * Bsz * Hd];
// weights
__device__ __align__(256) __nv_bfloat16 g_wih0h[(size_t)G3H * Hd];
__device__ __align__(256) __nv_bfloat16 g_wih0l[(size_t)G3H * Hd];
__device__ __align__(256) __nv_bfloat16 g_whh0h[(size_t)Cc * G3H * Hd];
__device__ __align__(256) __nv_bfloat16 g_whh0l[(size_t)Cc * G3H * Hd];
__device__ __align__(256) __nv_bfloat16 g_wihh[(size_t)(Ll-1) * Cc * G3H * Hd];
__device__ __align__(256) __nv_bfloat16 g_wihl[(size_t)(Ll-1) * Cc * G3H * Hd];
__device__ __align__(256) __nv_bfloat16 g_whhh[(size_t)(Ll-1) * Cc * G3H * Hd];
__device__ __align__(256) __nv_bfloat16 g_whhl[(size_t)(Ll-1) * Cc * G3H * Hd];
__device__ __align__(256) __nv_bfloat16 g_aiwh[(size_t)Ll * G3H * Hd];
__device__ __align__(256) __nv_bfloat16 g_aiwl[(size_t)Ll * G3H * Hd];
__device__ __align__(256) __nv_bfloat16 g_aowh[(size_t)Ll * Hd * Hd];
__device__ __align__(256) __nv_bfloat16 g_aowl[(size_t)Ll * Hd * Hd];
__device__ __align__(256) __nv_bfloat16 g_hwh [(size_t)Oo * Hd];
__device__ __align__(256) __nv_bfloat16 g_hwl [(size_t)Oo * Hd];

__device__ __forceinline__ float sigf(float x) { return 1.0f / (1.0f + expf(-x)); }

__device__ __forceinline__ uint32_t pack_bf16(__nv_bfloat16 a, __nv_bfloat16 b) {
    __nv_bfloat162 t = __nv_bfloat162(a, b);
    return *reinterpret_cast<uint32_t*>(&t);
}

__device__ __forceinline__ void store_split4(__nv_bfloat16* ph, __nv_bfloat16* pl,
                                             long off, float4 v) {
    __nv_bfloat16 h0 = __float2bfloat16(v.x);
    __nv_bfloat16 h1 = __float2bfloat16(v.y);
    __nv_bfloat16 h2 = __float2bfloat16(v.z);
    __nv_bfloat16 h3 = __float2bfloat16(v.w);
    *reinterpret_cast<uint2*>(ph + off) =
        make_uint2(pack_bf16(h0, h1), pack_bf16(h2, h3));
    __nv_bfloat16 l0 = __float2bfloat16(v.x - __bfloat162float(h0));
    __nv_bfloat16 l1 = __float2bfloat16(v.y - __bfloat162float(h1));
    __nv_bfloat16 l2 = __float2bfloat16(v.z - __bfloat162float(h2));
    __nv_bfloat16 l3 = __float2bfloat16(v.w - __bfloat162float(h3));
    *reinterpret_cast<uint2*>(pl + off) =
        make_uint2(pack_bf16(l0, l1), pack_bf16(l2, l3));
}

// store 2 values as split pair (4-byte writes)
__device__ __forceinline__ void store_split2(__nv_bfloat16* ph, __nv_bfloat16* pl,
                                             long off, float a, float b) {
    __nv_bfloat16 h0 = __float2bfloat16(a);
    __nv_bfloat16 h1 = __float2bfloat16(b);
    *reinterpret_cast<uint32_t*>(ph + off) = pack_bf16(h0, h1);
    __nv_bfloat16 l0 = __float2bfloat16(a - __bfloat162float(h0));
    __nv_bfloat16 l1 = __float2bfloat16(b - __bfloat162float(h1));
    *reinterpret_cast<uint32_t*>(pl + off) = pack_bf16(l0, l1);
}

// load 4 consecutive split values and reconstruct fp32 (hi + lo)
__device__ __forceinline__ float4 load_split4(const __nv_bfloat16* ph,
                                              const __nv_bfloat16* pl, long off) {
    uint2 uh = *reinterpret_cast<const uint2*>(ph + off);
    uint2 ul = *reinterpret_cast<const uint2*>(pl + off);
    __nv_bfloat162 h01 = *reinterpret_cast<__nv_bfloat162*>(&uh.x);
    __nv_bfloat162 h23 = *reinterpret_cast<__nv_bfloat162*>(&uh.y);
    __nv_bfloat162 l01 = *reinterpret_cast<__nv_bfloat162*>(&ul.x);
    __nv_bfloat162 l23 = *reinterpret_cast<__nv_bfloat162*>(&ul.y);
    float4 v;
    v.x = __bfloat162float(h01.x) + __bfloat162float(l01.x);
    v.y = __bfloat162float(h01.y) + __bfloat162float(l01.y);
    v.z = __bfloat162float(h23.x) + __bfloat162float(l23.x);
    v.w = __bfloat162float(h23.y) + __bfloat162float(l23.y);
    return v;
}

__device__ __forceinline__ float load_split1(const __nv_bfloat16* ph,
                                             const __nv_bfloat16* pl, long off) {
    return __bfloat162float(ph[off]) + __bfloat162float(pl[off]);
}

// ---------------- generic fp32 -> bf16 hi/lo split pass ---------------------
__global__ void split_pair(const float* __restrict__ in, __nv_bfloat16* __restrict__ oh,
                           __nv_bfloat16* __restrict__ ol)
{
    long i = (long)blockIdx.x * 256 + threadIdx.x;   // float4 index
    float4 v = reinterpret_cast<const float4*>(in)[i];
    store_split4(oh, ol, i * 4, v);
}

// ======================= HMMA (mma.sync) GEMM =======================
// CTA tile 128(b) x 64(g), 256 threads, 8 warps (4m x 2n), warp tile 32x32,
// 2 CTAs/SM. Term-major MMA ordering; 2-stage pipelined k-split fill.

#define KPAD    136
#define ROWB    (KPAD * 2)            // 272 bytes per row
#define TILE_A  ((size_t)128 * ROWB)
#define TILE_Bt ((size_t)64  * ROWB)
#define SM_AH   0
#define SM_AL   (SM_AH + TILE_A)
#define SM_BH   (SM_AL + TILE_A)
#define SM_BL   (SM_BH + TILE_Bt)
#define SM_TOT  (SM_BL + TILE_Bt)     // 104448 bytes

__device__ __forceinline__ uint32_t smem_u32(const void* p) {
    uint32_t a;
    asm("{ .reg .u64 t; cvta.to.shared.u64 t, %1; cvt.u32.u64 %0, t; }" : "=r"(a) : "l"(p));
    return a;
}
__device__ __forceinline__ void cpa16(uint32_t sdst, const void* gsrc) {
    asm volatile("cp.async.cg.shared.global [%0], [%1], 16;" :: "r"(sdst), "l"(gsrc));
}
#define CP_COMMIT() asm volatile("cp.async.commit_group;" ::: "memory")
#define CP_WAIT(n)  asm volatile("cp.async.wait_group %0;" :: "n"(n) : "memory")

__device__ __forceinline__ void mma16816(float* c, const uint32_t* a, const uint32_t* b) {
    asm volatile(
        "mma.sync.aligned.m16n8k16.row.col.f32.bf16.bf16.f32 "
        "{%0,%1,%2,%3}, {%4,%5,%6,%7}, {%8,%9}, {%0,%1,%2,%3};\n"
        : "+f"(c[0]), "+f"(c[1]), "+f"(c[2]), "+f"(c[3])
        : "r"(a[0]), "r"(a[1]), "r"(a[2]), "r"(a[3]), "r"(b[0]), "r"(b[1]));
}

#define LDSM_X4(r0, r1, r2, r3, addr) \
    asm volatile("ldmatrix.sync.aligned.m8n8.x4.shared.b16 {%0,%1,%2,%3}, [%4];" \
                 : "=r"(r0), "=r"(r1), "=r"(r2), "=r"(r3) : "r"(addr))

struct Frags {
    uint32_t ah[2][4];
    uint32_t al[2][4];
    uint32_t bh[4][2];
    uint32_t bl[4][2];
};

__device__ __forceinline__ void ld_frags(Frags& f, uint32_t aH, uint32_t aL,
                                         uint32_t bH, uint32_t bL) {
    #pragma unroll
    for (int i = 0; i < 2; i++)
        LDSM_X4(f.ah[i][0], f.ah[i][1], f.ah[i][2], f.ah[i][3], aH + i * (16 * ROWB));
    #pragma unroll
    for (int i = 0; i < 2; i++)
        LDSM_X4(f.al[i][0], f.al[i][1], f.al[i][2], f.al[i][3], aL + i * (16 * ROWB));
    LDSM_X4(f.bh[0][0], f.bh[0][1], f.bh[1][0], f.bh[1][1], bH);
    LDSM_X4(f.bh[2][0], f.bh[2][1], f.bh[3][0], f.bh[3][1], bH + 16 * ROWB);
    LDSM_X4(f.bl[0][0], f.bl[0][1], f.bl[1][0], f.bl[1][1], bL);
    LDSM_X4(f.bl[2][0], f.bl[2][1], f.bl[3][0], f.bl[3][1], bL + 16 * ROWB);
}

__device__ __forceinline__ void mma_all(float acc[2][4][4], Frags& f) {
    // term-major: 8 independent MMAs between accumulator reuses
    #pragma unroll
    for (int i = 0; i < 2; i++)
        #pragma unroll
        for (int j = 0; j < 4; j++)
            mma16816(acc[i][j], f.ah[i], f.bh[j]);
    #pragma unroll
    for (int i = 0; i < 2; i++)
        #pragma unroll
        for (int j = 0; j < 4; j++)
            mma16816(acc[i][j], f.ah[i], f.bl[j]);
    #pragma unroll
    for (int i = 0; i < 2; i++)
        #pragma unroll
        for (int j = 0; j < 4; j++)
            mma16816(acc[i][j], f.al[i], f.bh[j]);
}

// fill one k-half (chunks [h*8, h*8+8) of 16B per row) for A and B tiles
__device__ __forceinline__ void fill_half(
    uint32_t sb, int tid, int h,
    const __nv_bfloat16* a_h, const __nv_bfloat16* a_l,
    const __nv_bfloat16* b_h, const __nv_bfloat16* b_l)
{
    #pragma unroll 2
    for (int idx = tid; idx < 1024; idx += 256) {        // A: 128 rows x 8 chunks
        int r = idx >> 3, k = (idx & 7) + h * 8;
        cpa16(sb + SM_AH + r * ROWB + k * 16, a_h + (long)r * 128 + k * 8);
        cpa16(sb + SM_AL + r * ROWB + k * 16, a_l + (long)r * 128 + k * 8);
    }
    #pragma unroll 2
    for (int idx = tid; idx < 512; idx += 256) {         // B: 64 rows x 8 chunks
        int r = idx >> 3, k = (idx & 7) + h * 8;
        cpa16(sb + SM_BH + r * ROWB + k * 16, b_h + (long)r * 128 + k * 8);
        cpa16(sb + SM_BL + r * ROWB + k * 16, b_l + (long)r * 128 + k * 8);
    }
}

// mainloop: fills smem, runs MMAs, leaves result in acc
__device__ __forceinline__ void gemm_main(
    char* smem,
    const __nv_bfloat16* __restrict__ a_h, const __nv_bfloat16* __restrict__ a_l,
    const __nv_bfloat16* __restrict__ b_h, const __nv_bfloat16* __restrict__ b_l,
    float acc[2][4][4], int wm, int wn, int lane, int tid)
{
    uint32_t sb = smem_u32(smem);

    fill_half(sb, tid, 0, a_h, a_l, b_h, b_l);
    CP_COMMIT();
    fill_half(sb, tid, 1, a_h, a_l, b_h, b_l);
    CP_COMMIT();

    int a_lane = (wm + (lane & 7) + ((lane >> 3) & 1) * 8) * ROWB + (lane >> 4) * 16;
    int b_lane = (wn + (lane & 7) + ((lane >> 4) & 1) * 8) * ROWB + ((lane >> 3) & 1) * 16;

    uint32_t aH = sb + SM_AH + a_lane;
    uint32_t aL = sb + SM_AL + a_lane;
    uint32_t bH = sb + SM_BH + b_lane;
    uint32_t bL = sb + SM_BL + b_lane;

    #pragma unroll
    for (int i = 0; i < 2; i++)
        #pragma unroll
        for (int j = 0; j < 4; j++)
            #pragma unroll
            for (int r = 0; r < 4; r++) acc[i][j][r] = 0.0f;

    Frags fr[2];

    CP_WAIT(1);
    __syncthreads();
    ld_frags(fr[0], aH, aL, bH, bL);
    #pragma unroll
    for (int kk = 0; kk < 4; kk++) {
        if (kk < 3) {
            int ko = (kk + 1) * 32;
            ld_frags(fr[(kk + 1) & 1], aH + ko, aL + ko, bH + ko, bL + ko);
        }
        mma_all(acc, fr[kk & 1]);
    }

    CP_WAIT(0);
    __syncthreads();
    ld_frags(fr[0], aH + 128, aL + 128, bH + 128, bL + 128);
    #pragma unroll
    for (int kk = 0; kk < 4; kk++) {
        if (kk < 3) {
            int ko = 128 + (kk + 1) * 32;
            ld_frags(fr[(kk + 1) & 1], aH + ko, aL + ko, bH + ko, bL + ko);
        }
        mma_all(acc, fr[kk & 1]);
    }
}

// fp32-output GEMM (out-proj, head)
__global__ __launch_bounds__(256, 2) void gemm_tc(
    const __nv_bfloat16* __restrict__ Ah, const __nv_bfloat16* __restrict__ Al,
    const __nv_bfloat16* __restrict__ Bh, const __nv_bfloat16* __restrict__ Bl,
    const float* __restrict__ bias, float* __restrict__ Y,
    int G, long xStride, long wStride, long bStride, long yStride)
{
    extern __shared__ char smem[];
    int c = blockIdx.z;
    int b0 = blockIdx.x * 128;
    int g0 = blockIdx.y * 64;
    int tid = threadIdx.x, wid = tid >> 5, lane = tid & 31;
    int wm = (wid & 3) * 32, wn = (wid >> 2) * 32;

    bias += (long)c * bStride;
    Y    += (long)c * yStride;

    float acc[2][4][4];
    gemm_main(smem,
              Ah + (long)c * xStride + (long)b0 * 128,
              Al + (long)c * xStride + (long)b0 * 128,
              Bh + (long)c * wStride + (long)g0 * 128,
              Bl + (long)c * wStride + (long)g0 * 128,
              acc, wm, wn, lane, tid);

    int colb = g0 + wn + (lane & 3) * 2;
    #pragma unroll
    for (int i = 0; i < 2; i++) {
        int row = b0 + wm + i * 16 + (lane >> 2);
        #pragma unroll
        for (int j = 0; j < 4; j++) {
            int col = colb + j * 8;
            float bx = bias[col], by = bias[col + 1];
            float2 o0 = make_float2(acc[i][j][0] + bx, acc[i][j][1] + by);
            float2 o1 = make_float2(acc[i][j][2] + bx, acc[i][j][3] + by);
            *reinterpret_cast<float2*>(Y + (long)row * G + col)       = o0;
            *reinterpret_cast<float2*>(Y + (long)(row + 8) * G + col) = o1;
        }
    }
}

// split-output GEMM (qkv): writes bf16 hi/lo pair
__global__ __launch_bounds__(256, 2) void gemm_tc_sp(
    const __nv_bfloat16* __restrict__ Ah, const __nv_bfloat16* __restrict__ Al,
    const __nv_bfloat16* __restrict__ Bh, const __nv_bfloat16* __restrict__ Bl,
    const float* __restrict__ bias,
    __nv_bfloat16* __restrict__ Yh, __nv_bfloat16* __restrict__ Yl,
    long xStride, long wStride, long bStride, long yStride)
{
    extern __shared__ char smem[];
    int c = blockIdx.z;
    int b0 = blockIdx.x * 128;
    int g0 = blockIdx.y * 64;
    int tid = threadIdx.x, wid = tid >> 5, lane = tid & 31;
    int wm = (wid & 3) * 32, wn = (wid >> 2) * 32;

    bias += (long)c * bStride;
    Yh   += (long)c * yStride;
    Yl   += (long)c * yStride;

    float acc[2][4][4];
    gemm_main(smem,
              Ah + (long)c * xStride + (long)b0 * 128,
              Al + (long)c * xStride + (long)b0 * 128,
              Bh + (long)c * wStride + (long)g0 * 128,
              Bl + (long)c * wStride + (long)g0 * 128,
              acc, wm, wn, lane, tid);

    int colb = g0 + wn + (lane & 3) * 2;
    #pragma unroll
    for (int i = 0; i < 2; i++) {
        int row = b0 + wm + i * 16 + (lane >> 2);
        #pragma unroll
        for (int j = 0; j < 4; j++) {
            int col = colb + j * 8;
            float bx = bias[col], by = bias[col + 1];
            store_split2(Yh, Yl, (long)row * G3H + col,
                         acc[i][j][0] + bx, acc[i][j][1] + by);
            store_split2(Yh, Yl, (long)(row + 8) * G3H + col,
                         acc[i][j][2] + bx, acc[i][j][3] + by);
        }
    }
}

// dual split-output GEMM: z<Cc -> gi, else gh
__global__ __launch_bounds__(256, 2) void gemm_tc_dual_sp(
    const __nv_bfloat16* __restrict__ A1h, const __nv_bfloat16* __restrict__ A1l,
    const __nv_bfloat16* __restrict__ W1h, const __nv_bfloat16* __restrict__ W1l,
    const float* __restrict__ b1,
    __nv_bfloat16* __restrict__ Y1h, __nv_bfloat16* __restrict__ Y1l,
    const __nv_bfloat16* __restrict__ A2h, const __nv_bfloat16* __restrict__ A2l,
    const __nv_bfloat16* __restrict__ W2h, const __nv_bfloat16* __restrict__ W2l,
    const float* __restrict__ b2,
    __nv_bfloat16* __restrict__ Y2h, __nv_bfloat16* __restrict__ Y2l)
{
    extern __shared__ char smem[];
    int z  = blockIdx.z;
    int b0 = blockIdx.x * 128;
    int g0 = blockIdx.y * 64;
    int tid = threadIdx.x, wid = tid >> 5, lane = tid & 31;
    int wm = (wid & 3) * 32, wn = (wid >> 2) * 32;

    const __nv_bfloat16 *ah, *al, *wh, *wl;
    const float* bias;
    __nv_bfloat16 *Yh, *Yl;
    if (z < Cc) {
        int c = z;
        ah = A1h + (long)c * Bsz * Hd;  al = A1l + (long)c * Bsz * Hd;
        wh = W1h + (long)c * G3H * Hd;  wl = W1l + (long)c * G3H * Hd;
        bias = b1 + (long)c * G3H;
        Yh = Y1h + (long)c * Bsz * G3H; Yl = Y1l + (long)c * Bsz * G3H;
    } else {
        int c = z - Cc;
        ah = A2h + (long)c * Bsz * Hd;  al = A2l + (long)c * Bsz * Hd;
        wh = W2h + (long)c * G3H * Hd;  wl = W2l + (long)c * G3H * Hd;
        bias = b2 + (long)c * G3H;
        Yh = Y2h + (long)c * Bsz * G3H; Yl = Y2l + (long)c * Bsz * G3H;
    }

    float acc[2][4][4];
    gemm_main(smem, ah + (long)b0 * 128, al + (long)b0 * 128,
              wh + (long)g0 * 128, wl + (long)g0 * 128,
              acc, wm, wn, lane, tid);

    int colb = g0 + wn + (lane & 3) * 2;
    #pragma unroll
    for (int i = 0; i < 2; i++) {
        int row = b0 + wm + i * 16 + (lane >> 2);
        #pragma unroll
        for (int j = 0; j < 4; j++) {
            int col = colb + j * 8;
            float bx = bias[col], by = bias[col + 1];
            store_split2(Yh, Yl, (long)row * G3H + col,
                         acc[i][j][0] + bx, acc[i][j][1] + by);
            store_split2(Yh, Yl, (long)(row + 8) * G3H + col,
                         acc[i][j][2] + bx, acc[i][j][3] + by);
        }
    }
}

// ---------------- embedding gather -> bf16 hi/lo split -----------------------
__global__ void gather_x0(const int* __restrict__ tok, const float* __restrict__ emb)
{
    long t = (long)blockIdx.x * 256 + threadIdx.x;   // B*32 threads
    int b  = (int)(t >> 5);
    int e4 = (int)(t & 31) << 2;
    float4 v = *(const float4*)(emb + (long)tok[b] * 128 + e4);
    store_split4(g_x0h, g_x0l, (long)b * 128 + e4, v);
}

// ---------------- GRU elementwise: split in, split out -----------------------
// l0bias != nullptr => layer 0: for cells c>0, gi is pure bias (read directly).
__global__ void gru_kernel(const float* __restrict__ hprev,
                           const float* __restrict__ l0bias)
{
    long t   = (long)blockIdx.x * 256 + threadIdx.x;
    long row = t >> 5;
    int  h4  = (int)(t & 31) << 2;
    int  c   = (int)(row >> 14);      // row / Bsz

    float4 ir, iz, inn;
    if (l0bias != nullptr && c > 0) {
        const float* gi = l0bias + (long)c * G3H;
        ir  = *(const float4*)(gi + h4);
        iz  = *(const float4*)(gi + 128 + h4);
        inn = *(const float4*)(gi + 256 + h4);
    } else {
        long gb = row * G3H;
        ir  = load_split4(g_gih, g_gil, gb + h4);
        iz  = load_split4(g_gih, g_gil, gb + 128 + h4);
        inn = load_split4(g_gih, g_gil, gb + 256 + h4);
    }
    long gb = row * G3H;
    float4 hr  = load_split4(g_ghh, g_ghl, gb + h4);
    float4 hz  = load_split4(g_ghh, g_ghl, gb + 128 + h4);
    float4 hnn = load_split4(g_ghh, g_ghl, gb + 256 + h4);
    float4 hp  = *(const float4*)(hprev + row * 128 + h4);

    float4 out;
    {
        float r = sigf(ir.x + hr.x), z = sigf(iz.x + hz.x);
        float n = tanhf(inn.x + r * hnn.x);
        out.x = (1.0f - z) * n + z * hp.x;
    }
    {
        float r = sigf(ir.y + hr.y), z = sigf(iz.y + hz.y);
        float n = tanhf(inn.y + r * hnn.y);
        out.y = (1.0f - z) * n + z * hp.y;
    }
    {
        float r = sigf(ir.z + hr.z), z = sigf(iz.z + hz.z);
        float n = tanhf(inn.z + r * hnn.z);
        out.z = (1.0f - z) * n + z * hp.z;
    }
    {
        float r = sigf(ir.w + hr.w), z = sigf(iz.w + hz.w);
        float n = tanhf(inn.w + r * hnn.w);
        out.w = (1.0f - z) * n + z * hp.w;
    }
    store_split4(g_nh, g_nl, row * 128 + h4, out);
}

// ---------------- tiny attention over C=4 positions (split in/out) -----------
__global__ void attn_kernel()
{
    int gw   = blockIdx.x * 4 + (threadIdx.x >> 5);
    int lane = threadIdx.x & 31;
    int b  = gw >> 2;
    int nh = gw & 3;

    float q[4], k[4], v[4];
    #pragma unroll
    for (int c = 0; c < 4; c++) {
        long p = ((long)c * Bsz + b) * G3H + nh * 32 + lane;
        q[c] = load_split1(g_qkh, g_qkl, p);
        k[c] = load_split1(g_qkh, g_qkl, p + 128);
        v[c] = load_split1(g_qkh, g_qkl, p + 256);
    }

    float s[4][4];
    #pragma unroll
    for (int qc = 0; qc < 4; qc++) {
        #pragma unroll
        for (int kc = 0; kc < 4; kc++) {
            float p = q[qc] * k[kc];
            #pragma unroll
            for (int off = 16; off > 0; off >>= 1)
                p += __shfl_xor_sync(0xFFFFFFFFu, p, off);
            s[qc][kc] = p * 0.17677669529663687f;   // 1/sqrt(32)
        }
    }

    #pragma unroll
    for (int qc = 0; qc < 4; qc++) {
        float m = fmaxf(fmaxf(s[qc][0], s[qc][1]), fmaxf(s[qc][2], s[qc][3]));
        float e0 = expf(s[qc][0] - m), e1 = expf(s[qc][1] - m);
        float e2 = expf(s[qc][2] - m), e3 = expf(s[qc][3] - m);
        float inv = 1.0f / (e0 + e1 + e2 + e3);
        float o = (e0 * v[0] + e1 * v[1] + e2 * v[2] + e3 * v[3]) * inv;
        long off = ((long)qc * Bsz + b) * 128 + nh * 32 + lane;
        __nv_bfloat16 h = __float2bfloat16(o);
        g_aah[off] = h;
        g_aal[off] = __float2bfloat16(o - __bfloat162float(h));
    }
}

// ---------------- fused LayerNorm + gate + blend -----------------------------
// hn is reconstructed from the bf16 hi/lo split (g_nh + g_nl).
__global__ void lngate_kernel(const float* __restrict__ gg, const float* __restrict__ bb,
                              const float* __restrict__ gw, const float* __restrict__ gbp,
                              float* __restrict__ hout)
{
    int row  = blockIdx.x * 4 + (threadIdx.x >> 5);
    int lane = threadIdx.x & 31;
    const float* mp = g_msg + (long)row * 128;
    long hoff = (long)row * 128 + lane * 4;

    float4 x = *(const float4*)(mp + lane * 4);
    float s = x.x + x.y + x.z + x.w;
    #pragma unroll
    for (int off = 16; off > 0; off >>= 1) s += __shfl_xor_sync(0xFFFFFFFFu, s, off);
    float mean = s * (1.0f / 128.0f);

    float dx = x.x - mean, dy = x.y - mean, dz = x.z - mean, dw = x.w - mean;
    float sq = dx * dx + dy * dy + dz * dz + dw * dw;
    #pragma unroll
    for (int off = 16; off > 0; off >>= 1) sq += __shfl_xor_sync(0xFFFFFFFFu, sq, off);
    float rstd = rsqrtf(sq * (1.0f / 128.0f) + 1e-5f);

    float4 gv = *(const float4*)(gg + lane * 4);
    float4 bv = *(const float4*)(bb + lane * 4);
    float4 m;
    m.x = dx * rstd * gv.x + bv.x;
    m.y = dy * rstd * gv.y + bv.y;
    m.z = dz * rstd * gv.z + bv.z;
    m.w = dw * rstd * gv.w + bv.w;

    float4 hv = load_split4(g_nh, g_nl, hoff);
    float4 w1 = *(const float4*)(gw + lane * 4);
    float4 w2 = *(const float4*)(gw + 128 + lane * 4);

    float p = hv.x * w1.x + hv.y * w1.y + hv.z * w1.z + hv.w * w1.w
            + m.x * w2.x + m.y * w2.y + m.z * w2.z + m.w * w2.w;
    #pragma unroll
    for (int off = 16; off > 0; off >>= 1) p += __shfl_xor_sync(0xFFFFFFFFu, p, off);
    float gt = sigf(p + gbp[0]);

    float4 o;
    o.x = (1.0f - gt) * hv.x + gt * m.x;
    o.y = (1.0f - gt) * hv.y + gt * m.y;
    o.z = (1.0f - gt) * hv.z + gt * m.z;
    o.w = (1.0f - gt) * hv.w + gt * m.w;
    *(float4*)(hout + hoff) = o;
    store_split4(g_ph, g_pl, hoff, o);
}

// ---------------- host orchestration ----------------------------------------
extern "C" void kernel_launch(void* const* d_in, const int* in_sizes, int n_in,
                              void* d_out, int out_size)
{
    const int*   tokens     = (const int*)  d_in[0];
    const float* h_in       = (const float*)d_in[1];
    const float* emb        = (const float*)d_in[2];
    const float* wih0_c0    = (const float*)d_in[3];
    const float* bih0       = (const float*)d_in[5];
    const float* whh0       = (const float*)d_in[6];
    const float* bhh0       = (const float*)d_in[7];
    const float* wih        = (const float*)d_in[8];
    const float* whh        = (const float*)d_in[9];
    const float* bih        = (const float*)d_in[10];
    const float* bhh        = (const float*)d_in[11];
    const float* attn_in_w  = (const float*)d_in[12];
    const float* attn_in_b  = (const float*)d_in[13];
    const float* attn_out_w = (const float*)d_in[14];
    const float* attn_out_b = (const float*)d_in[15];
    const float* ln_g       = (const float*)d_in[16];
    const float* ln_b       = (const float*)d_in[17];
    const float* gate_w     = (const float*)d_in[18];
    const float* gate_b     = (const float*)d_in[19];
    const float* head_w     = (const float*)d_in[20];
    const float* head_b     = (const float*)d_in[21];

    float* yOut = (float*)d_out;                       // (B, O)
    float* hOut = yOut + (size_t)Bsz * Oo;             // (L, C, B, H)

    float* pmsg;
    cudaGetSymbolAddress((void**)&pmsg, g_msg);

    __nv_bfloat16 *gih, *gil, *ghh, *ghl, *qkh, *qkl;
    __nv_bfloat16 *x0h, *x0l, *hh, *hl, *nh, *nl, *aah, *aal, *ph, *pl;
    __nv_bfloat16 *wih0h, *wih0l, *whh0h, *whh0l, *wihh, *wihl, *whhh, *whhl;
    __nv_bfloat16 *aiwh, *aiwl, *aowh, *aowl, *hwh, *hwl;
    cudaGetSymbolAddress((void**)&gih, g_gih);   cudaGetSymbolAddress((void**)&gil, g_gil);
    cudaGetSymbolAddress((void**)&ghh, g_ghh);   cudaGetSymbolAddress((void**)&ghl, g_ghl);
    cudaGetSymbolAddress((void**)&qkh, g_qkh);   cudaGetSymbolAddress((void**)&qkl, g_qkl);
    cudaGetSymbolAddress((void**)&x0h, g_x0h);   cudaGetSymbolAddress((void**)&x0l, g_x0l);
    cudaGetSymbolAddress((void**)&hh,  g_hh);    cudaGetSymbolAddress((void**)&hl,  g_hl);
    cudaGetSymbolAddress((void**)&nh,  g_nh);    cudaGetSymbolAddress((void**)&nl,  g_nl);
    cudaGetSymbolAddress((void**)&aah, g_aah);   cudaGetSymbolAddress((void**)&aal, g_aal);
    cudaGetSymbolAddress((void**)&ph,  g_ph);    cudaGetSymbolAddress((void**)&pl,  g_pl);
    cudaGetSymbolAddress((void**)&wih0h, g_wih0h); cudaGetSymbolAddress((void**)&wih0l, g_wih0l);
    cudaGetSymbolAddress((void**)&whh0h, g_whh0h); cudaGetSymbolAddress((void**)&whh0l, g_whh0l);
    cudaGetSymbolAddress((void**)&wihh, g_wihh); cudaGetSymbolAddress((void**)&wihl, g_wihl);
    cudaGetSymbolAddress((void**)&whhh, g_whhh); cudaGetSymbolAddress((void**)&whhl, g_whhl);
    cudaGetSymbolAddress((void**)&aiwh, g_aiwh); cudaGetSymbolAddress((void**)&aiwl, g_aiwl);
    cudaGetSymbolAddress((void**)&aowh, g_aowh); cudaGetSymbolAddress((void**)&aowl, g_aowl);
    cudaGetSymbolAddress((void**)&hwh,  g_hwh);  cudaGetSymbolAddress((void**)&hwl,  g_hwl);

    cudaFuncSetAttribute(gemm_tc,         cudaFuncAttributeMaxDynamicSharedMemorySize, SM_TOT);
    cudaFuncSetAttribute(gemm_tc_sp,      cudaFuncAttributeMaxDynamicSharedMemorySize, SM_TOT);
    cudaFuncSetAttribute(gemm_tc_dual_sp, cudaFuncAttributeMaxDynamicSharedMemorySize, SM_TOT);

    const long CBH = (long)Cc * Bsz * Hd;
    (void)in_sizes; (void)n_in; (void)out_size;

    // ---- prolog: split weights + h into bf16 hi/lo ----
    #define SPLIT(src, dh, dl, nelem) \
        split_pair<<<(int)((nelem) / 1024), 256>>>(src, dh, dl)
    SPLIT(wih0_c0,   wih0h, wih0l, (long)G3H * Hd);
    SPLIT(whh0,      whh0h, whh0l, (long)Cc * G3H * Hd);
    SPLIT(wih,       wihh,  wihl,  (long)(Ll-1) * Cc * G3H * Hd);
    SPLIT(whh,       whhh,  whhl,  (long)(Ll-1) * Cc * G3H * Hd);
    SPLIT(attn_in_w, aiwh,  aiwl,  (long)Ll * G3H * Hd);
    SPLIT(attn_out_w,aowh,  aowl,  (long)Ll * Hd * Hd);
    SPLIT(head_w,    hwh,   hwl,   (long)Oo * Hd);
    SPLIT(h_in,      hh,    hl,    (long)Ll * CBH);
    #undef SPLIT
    gather_x0<<<(Bsz * 32) / 256, 256>>>(tokens, emb);

    dim3 gB(Bsz / 128, G3H / 64, Cc);
    dim3 gD(Bsz / 128, G3H / 64, 2 * Cc);
    dim3 gO(Bsz / 128, Hd  / 64, Cc);

    for (int l = 0; l < Ll; l++) {
        const float* hlp = h_in + (size_t)l * CBH;

        // ---- gi + gh (split outputs) ----
        if (l == 0) {
            dim3 g1(Bsz / 128, G3H / 64, 1);
            gemm_tc_sp<<<g1, 256, SM_TOT>>>(x0h, x0l, wih0h, wih0l, bih0,
                                            gih, gil, 0, 0, 0, 0);
            gemm_tc_sp<<<gB, 256, SM_TOT>>>(hh, hl, whh0h, whh0l, bhh0,
                                            ghh, ghl,
                                            (long)Bsz * Hd, (long)G3H * Hd, G3H,
                                            (long)Bsz * G3H);
        } else {
            gemm_tc_dual_sp<<<gD, 256, SM_TOT>>>(
                ph, pl,
                wihh + (size_t)(l - 1) * Cc * G3H * Hd,
                wihl + (size_t)(l - 1) * Cc * G3H * Hd,
                bih + (size_t)(l - 1) * Cc * G3H, gih, gil,
                hh + (size_t)l * CBH, hl + (size_t)l * CBH,
                whhh + (size_t)(l - 1) * Cc * G3H * Hd,
                whhl + (size_t)(l - 1) * Cc * G3H * Hd,
                bhh + (size_t)(l - 1) * Cc * G3H, ghh, ghl);
        }

        // ---- GRU (l=0: cells 1..3 read bias directly) ----
        gru_kernel<<<((long)Cc * Bsz * 32) / 256, 256>>>(
            hlp, (l == 0) ? bih0 : nullptr);

        // ---- QKV (split output) ----
        gemm_tc_sp<<<gB, 256, SM_TOT>>>(nh, nl,
                                        aiwh + (size_t)l * G3H * Hd,
                                        aiwl + (size_t)l * G3H * Hd,
                                        attn_in_b + (size_t)l * G3H,
                                        qkh, qkl,
                                        (long)Bsz * Hd, 0, 0, (long)Bsz * G3H);

        // ---- attention ----
        attn_kernel<<<(Bsz * NHh) / 4, 128>>>();

        // ---- out projection (fp32 out: LN needs exactness less, keep) ----
        gemm_tc<<<gO, 256, SM_TOT>>>(aah, aal,
                                     aowh + (size_t)l * Hd * Hd,
                                     aowl + (size_t)l * Hd * Hd,
                                     attn_out_b + (size_t)l * Hd,
                                     pmsg, Hd,
                                     (long)Bsz * Hd, 0, 0, (long)Bsz * Hd);

        // ---- fused LN + gate + blend -> hOut + g_ph/g_pl split ----
        lngate_kernel<<<(Cc * Bsz) / 4, 128>>>(ln_g + (size_t)l * Hd, ln_b + (size_t)l * Hd,
                                               gate_w + (size_t)l * 2 * Hd, gate_b + l,
                                               hOut + (size_t)l * CBH);
    }

    // ---- head: y = h_n[L-1, 0] @ head_w.T + head_b ----
    dim3 gH(Bsz / 128, Oo / 64, 1);
    gemm_tc<<<gH, 256, SM_TOT>>>(ph, pl, hwh, hwl, head_b, yOut, Oo, 0, 0, 0, 0);
}

// round 15
// speedup vs baseline: 1.1104x; 1.1104x over previous
#include <cuda_runtime.h>
#include <cuda_bf16.h>
#include <math.h>
#include <stdint.h>

#define Bsz 16384
#define Hd  128
#define Cc  4
#define Ll  6
#define NHh 4
#define HDd 32
#define Oo  1024
#define G3H 384

// ---------------- fp32 scratch ----------------------------------------------
__device__ __align__(256) float g_gi [(size_t)Cc * Bsz * G3H];
__device__ __align__(256) float g_gh [(size_t)Cc * Bsz * G3H];
__device__ __align__(256) float g_qkv[(size_t)Cc * Bsz * G3H];
__device__ __align__(256) float g_msg[(size_t)Cc * Bsz * Hd];

// ---------------- bf16 hi/lo split buffers ----------------------------------
__device__ __align__(256) __nv_bfloat16 g_x0h[(size_t)Bsz * Hd];
__device__ __align__(256) __nv_bfloat16 g_x0l[(size_t)Bsz * Hd];
__device__ __align__(256) __nv_bfloat16 g_hh [(size_t)Ll * Cc * Bsz * Hd];  // h_in split
__device__ __align__(256) __nv_bfloat16 g_hl [(size_t)Ll * Cc * Bsz * Hd];
__device__ __align__(256) __nv_bfloat16 g_nh [(size_t)Cc * Bsz * Hd];       // hn split
__device__ __align__(256) __nv_bfloat16 g_nl [(size_t)Cc * Bsz * Hd];
__device__ __align__(256) __nv_bfloat16 g_aah[(size_t)Cc * Bsz * Hd];       // att split
__device__ __align__(256) __nv_bfloat16 g_aal[(size_t)Cc * Bsz * Hd];
__device__ __align__(256) __nv_bfloat16 g_ph [(size_t)Cc * Bsz * Hd];       // hOut split
__device__ __align__(256) __nv_bfloat16 g_pl [(size_t)Cc * Bsz * Hd];
// weights
__device__ __align__(256) __nv_bfloat16 g_wih0h[(size_t)G3H * Hd];
__device__ __align__(256) __nv_bfloat16 g_wih0l[(size_t)G3H * Hd];
__device__ __align__(256) __nv_bfloat16 g_whh0h[(size_t)Cc * G3H * Hd];
__device__ __align__(256) __nv_bfloat16 g_whh0l[(size_t)Cc * G3H * Hd];
__device__ __align__(256) __nv_bfloat16 g_wihh[(size_t)(Ll-1) * Cc * G3H * Hd];
__device__ __align__(256) __nv_bfloat16 g_wihl[(size_t)(Ll-1) * Cc * G3H * Hd];
__device__ __align__(256) __nv_bfloat16 g_whhh[(size_t)(Ll-1) * Cc * G3H * Hd];
__device__ __align__(256) __nv_bfloat16 g_whhl[(size_t)(Ll-1) * Cc * G3H * Hd];
__device__ __align__(256) __nv_bfloat16 g_aiwh[(size_t)Ll * G3H * Hd];
__device__ __align__(256) __nv_bfloat16 g_aiwl[(size_t)Ll * G3H * Hd];
__device__ __align__(256) __nv_bfloat16 g_aowh[(size_t)Ll * Hd * Hd];
__device__ __align__(256) __nv_bfloat16 g_aowl[(size_t)Ll * Hd * Hd];
__device__ __align__(256) __nv_bfloat16 g_hwh [(size_t)Oo * Hd];
__device__ __align__(256) __nv_bfloat16 g_hwl [(size_t)Oo * Hd];

__device__ __forceinline__ float sigf(float x) { return 1.0f / (1.0f + expf(-x)); }

__device__ __forceinline__ uint32_t pack_bf16(__nv_bfloat16 a, __nv_bfloat16 b) {
    __nv_bfloat162 t = __nv_bfloat162(a, b);
    return *reinterpret_cast<uint32_t*>(&t);
}

__device__ __forceinline__ void store_split4(__nv_bfloat16* ph, __nv_bfloat16* pl,
                                             long off, float4 v) {
    __nv_bfloat16 h0 = __float2bfloat16(v.x);
    __nv_bfloat16 h1 = __float2bfloat16(v.y);
    __nv_bfloat16 h2 = __float2bfloat16(v.z);
    __nv_bfloat16 h3 = __float2bfloat16(v.w);
    *reinterpret_cast<uint2*>(ph + off) =
        make_uint2(pack_bf16(h0, h1), pack_bf16(h2, h3));
    __nv_bfloat16 l0 = __float2bfloat16(v.x - __bfloat162float(h0));
    __nv_bfloat16 l1 = __float2bfloat16(v.y - __bfloat162float(h1));
    __nv_bfloat16 l2 = __float2bfloat16(v.z - __bfloat162float(h2));
    __nv_bfloat16 l3 = __float2bfloat16(v.w - __bfloat162float(h3));
    *reinterpret_cast<uint2*>(pl + off) =
        make_uint2(pack_bf16(l0, l1), pack_bf16(l2, l3));
}

// load 4 consecutive split values and reconstruct fp32 (hi + lo)
__device__ __forceinline__ float4 load_split4(const __nv_bfloat16* ph,
                                              const __nv_bfloat16* pl, long off) {
    uint2 uh = *reinterpret_cast<const uint2*>(ph + off);
    uint2 ul = *reinterpret_cast<const uint2*>(pl + off);
    __nv_bfloat162 h01 = *reinterpret_cast<__nv_bfloat162*>(&uh.x);
    __nv_bfloat162 h23 = *reinterpret_cast<__nv_bfloat162*>(&uh.y);
    __nv_bfloat162 l01 = *reinterpret_cast<__nv_bfloat162*>(&ul.x);
    __nv_bfloat162 l23 = *reinterpret_cast<__nv_bfloat162*>(&ul.y);
    float4 v;
    v.x = __bfloat162float(h01.x) + __bfloat162float(l01.x);
    v.y = __bfloat162float(h01.y) + __bfloat162float(l01.y);
    v.z = __bfloat162float(h23.x) + __bfloat162float(l23.x);
    v.w = __bfloat162float(h23.y) + __bfloat162float(l23.y);
    return v;
}

// ---------------- generic fp32 -> bf16 hi/lo split pass ---------------------
__global__ void split_pair(const float* __restrict__ in, __nv_bfloat16* __restrict__ oh,
                           __nv_bfloat16* __restrict__ ol)
{
    long i = (long)blockIdx.x * 256 + threadIdx.x;   // float4 index
    float4 v = reinterpret_cast<const float4*>(in)[i];
    store_split4(oh, ol, i * 4, v);
}

// ======================= HMMA (mma.sync) GEMM =======================
// CTA tile 128(b) x 64(g), 256 threads, 8 warps (4m x 2n), warp tile 32x32,
// 2 CTAs/SM. Term-major MMA ordering; 4-stage pipelined k-split fill.

#define KPAD    136
#define ROWB    (KPAD * 2)            // 272 bytes per row
#define TILE_A  ((size_t)128 * ROWB)
#define TILE_Bt ((size_t)64  * ROWB)
#define SM_AH   0
#define SM_AL   (SM_AH + TILE_A)
#define SM_BH   (SM_AL + TILE_A)
#define SM_BL   (SM_BH + TILE_Bt)
#define SM_TOT  (SM_BL + TILE_Bt)     // 104448 bytes

__device__ __forceinline__ uint32_t smem_u32(const void* p) {
    uint32_t a;
    asm("{ .reg .u64 t; cvta.to.shared.u64 t, %1; cvt.u32.u64 %0, t; }" : "=r"(a) : "l"(p));
    return a;
}
__device__ __forceinline__ void cpa16(uint32_t sdst, const void* gsrc) {
    asm volatile("cp.async.cg.shared.global [%0], [%1], 16;" :: "r"(sdst), "l"(gsrc));
}
#define CP_COMMIT() asm volatile("cp.async.commit_group;" ::: "memory")
#define CP_WAIT(n)  asm volatile("cp.async.wait_group %0;" :: "n"(n) : "memory")

__device__ __forceinline__ void mma16816(float* c, const uint32_t* a, const uint32_t* b) {
    asm volatile(
        "mma.sync.aligned.m16n8k16.row.col.f32.bf16.bf16.f32 "
        "{%0,%1,%2,%3}, {%4,%5,%6,%7}, {%8,%9}, {%0,%1,%2,%3};\n"
        : "+f"(c[0]), "+f"(c[1]), "+f"(c[2]), "+f"(c[3])
        : "r"(a[0]), "r"(a[1]), "r"(a[2]), "r"(a[3]), "r"(b[0]), "r"(b[1]));
}

#define LDSM_X4(r0, r1, r2, r3, addr) \
    asm volatile("ldmatrix.sync.aligned.m8n8.x4.shared.b16 {%0,%1,%2,%3}, [%4];" \
                 : "=r"(r0), "=r"(r1), "=r"(r2), "=r"(r3) : "r"(addr))

struct Frags {
    uint32_t ah[2][4];
    uint32_t al[2][4];
    uint32_t bh[4][2];
    uint32_t bl[4][2];
};

__device__ __forceinline__ void ld_frags(Frags& f, uint32_t aH, uint32_t aL,
                                         uint32_t bH, uint32_t bL) {
    #pragma unroll
    for (int i = 0; i < 2; i++)
        LDSM_X4(f.ah[i][0], f.ah[i][1], f.ah[i][2], f.ah[i][3], aH + i * (16 * ROWB));
    #pragma unroll
    for (int i = 0; i < 2; i++)
        LDSM_X4(f.al[i][0], f.al[i][1], f.al[i][2], f.al[i][3], aL + i * (16 * ROWB));
    LDSM_X4(f.bh[0][0], f.bh[0][1], f.bh[1][0], f.bh[1][1], bH);
    LDSM_X4(f.bh[2][0], f.bh[2][1], f.bh[3][0], f.bh[3][1], bH + 16 * ROWB);
    LDSM_X4(f.bl[0][0], f.bl[0][1], f.bl[1][0], f.bl[1][1], bL);
    LDSM_X4(f.bl[2][0], f.bl[2][1], f.bl[3][0], f.bl[3][1], bL + 16 * ROWB);
}

__device__ __forceinline__ void mma_all(float acc[2][4][4], Frags& f) {
    // term-major: 8 independent MMAs between accumulator reuses
    #pragma unroll
    for (int i = 0; i < 2; i++)
        #pragma unroll
        for (int j = 0; j < 4; j++)
            mma16816(acc[i][j], f.ah[i], f.bh[j]);
    #pragma unroll
    for (int i = 0; i < 2; i++)
        #pragma unroll
        for (int j = 0; j < 4; j++)
            mma16816(acc[i][j], f.ah[i], f.bl[j]);
    #pragma unroll
    for (int i = 0; i < 2; i++)
        #pragma unroll
        for (int j = 0; j < 4; j++)
            mma16816(acc[i][j], f.al[i], f.bh[j]);
}

// fill one k-quarter (chunks [q*4, q*4+4) of 16B per row) for A and B tiles
__device__ __forceinline__ void fill_q(
    uint32_t sb, int tid, int q,
    const __nv_bfloat16* a_h, const __nv_bfloat16* a_l,
    const __nv_bfloat16* b_h, const __nv_bfloat16* b_l)
{
    #pragma unroll 2
    for (int idx = tid; idx < 512; idx += 256) {        // A: 128 rows x 4 chunks
        int r = idx >> 2, k = (idx & 3) + q * 4;
        cpa16(sb + SM_AH + r * ROWB + k * 16, a_h + (long)r * 128 + k * 8);
        cpa16(sb + SM_AL + r * ROWB + k * 16, a_l + (long)r * 128 + k * 8);
    }
    {                                                   // B: 64 rows x 4 chunks = 256
        int idx = tid;
        int r = idx >> 2, k = (idx & 3) + q * 4;
        cpa16(sb + SM_BH + r * ROWB + k * 16, b_h + (long)r * 128 + k * 8);
        cpa16(sb + SM_BL + r * ROWB + k * 16, b_l + (long)r * 128 + k * 8);
    }
}

// shared GEMM body: 4-stage pipelined fill, term-major mainloop, epilogue
__device__ __forceinline__ void gemm_body(
    char* smem,
    const __nv_bfloat16* __restrict__ a_h, const __nv_bfloat16* __restrict__ a_l,
    const __nv_bfloat16* __restrict__ b_h, const __nv_bfloat16* __restrict__ b_l,
    const float* __restrict__ bias, float* __restrict__ Y,
    int G, int b0, int g0)
{
    int tid  = threadIdx.x;
    int wid  = tid >> 5;
    int lane = tid & 31;
    uint32_t sb = smem_u32(smem);

    fill_q(sb, tid, 0, a_h, a_l, b_h, b_l);
    CP_COMMIT();
    fill_q(sb, tid, 1, a_h, a_l, b_h, b_l);
    CP_COMMIT();
    fill_q(sb, tid, 2, a_h, a_l, b_h, b_l);
    CP_COMMIT();
    fill_q(sb, tid, 3, a_h, a_l, b_h, b_l);
    CP_COMMIT();

    int wm = (wid & 3) * 32;
    int wn = (wid >> 2) * 32;

    int a_lane = (wm + (lane & 7) + ((lane >> 3) & 1) * 8) * ROWB + (lane >> 4) * 16;
    int b_lane = (wn + (lane & 7) + ((lane >> 4) & 1) * 8) * ROWB + ((lane >> 3) & 1) * 16;

    uint32_t aH = sb + SM_AH + a_lane;
    uint32_t aL = sb + SM_AL + a_lane;
    uint32_t bH = sb + SM_BH + b_lane;
    uint32_t bL = sb + SM_BL + b_lane;

    float acc[2][4][4];
    #pragma unroll
    for (int i = 0; i < 2; i++)
        #pragma unroll
        for (int j = 0; j < 4; j++)
            #pragma unroll
            for (int r = 0; r < 4; r++) acc[i][j][r] = 0.0f;

    Frags fr[2];

    // quarter q covers k-steps 2q, 2q+1 (byte offset 64q within the row)
    #define QUARTER(q, w) \
        CP_WAIT(w); \
        __syncthreads(); \
        ld_frags(fr[0], aH + (q)*64,      aL + (q)*64,      bH + (q)*64,      bL + (q)*64); \
        ld_frags(fr[1], aH + (q)*64 + 32, aL + (q)*64 + 32, bH + (q)*64 + 32, bL + (q)*64 + 32); \
        mma_all(acc, fr[0]); \
        mma_all(acc, fr[1]);

    QUARTER(0, 3)
    QUARTER(1, 2)
    QUARTER(2, 1)
    QUARTER(3, 0)
    #undef QUARTER

    int colb = g0 + wn + (lane & 3) * 2;
    #pragma unroll
    for (int i = 0; i < 2; i++) {
        int row = b0 + wm + i * 16 + (lane >> 2);
        #pragma unroll
        for (int j = 0; j < 4; j++) {
            int col = colb + j * 8;
            float bx = bias[col], by = bias[col + 1];
            float2 o0 = make_float2(acc[i][j][0] + bx, acc[i][j][1] + by);
            float2 o1 = make_float2(acc[i][j][2] + bx, acc[i][j][3] + by);
            *reinterpret_cast<float2*>(Y + (long)row * G + col)       = o0;
            *reinterpret_cast<float2*>(Y + (long)(row + 8) * G + col) = o1;
        }
    }
}

__global__ __launch_bounds__(256, 2) void gemm_tc(
    const __nv_bfloat16* __restrict__ Ah, const __nv_bfloat16* __restrict__ Al,
    const __nv_bfloat16* __restrict__ Bh, const __nv_bfloat16* __restrict__ Bl,
    const float* __restrict__ bias, float* __restrict__ Y,
    int G, long xStride, long wStride, long bStride, long yStride)
{
    extern __shared__ char smem[];
    int c = blockIdx.z;
    int b0 = blockIdx.x * 128;
    int g0 = blockIdx.y * 64;
    gemm_body(smem,
              Ah + (long)c * xStride + (long)b0 * 128,
              Al + (long)c * xStride + (long)b0 * 128,
              Bh + (long)c * wStride + (long)g0 * 128,
              Bl + (long)c * wStride + (long)g0 * 128,
              bias + (long)c * bStride,
              Y + (long)c * yStride, G, b0, g0);
}

// dual-set GEMM: z in [0, 2*Cc); z<Cc -> set1 (gi), else set2 (gh).
__global__ __launch_bounds__(256, 2) void gemm_tc_dual(
    const __nv_bfloat16* __restrict__ A1h, const __nv_bfloat16* __restrict__ A1l,
    const __nv_bfloat16* __restrict__ W1h, const __nv_bfloat16* __restrict__ W1l,
    const float* __restrict__ b1, float* __restrict__ Y1,
    const __nv_bfloat16* __restrict__ A2h, const __nv_bfloat16* __restrict__ A2l,
    const __nv_bfloat16* __restrict__ W2h, const __nv_bfloat16* __restrict__ W2l,
    const float* __restrict__ b2, float* __restrict__ Y2)
{
    extern __shared__ char smem[];
    int z  = blockIdx.z;
    int b0 = blockIdx.x * 128;
    int g0 = blockIdx.y * 64;
    const __nv_bfloat16 *ah, *al, *wh, *wl;
    const float* bias;
    float* Y;
    if (z < Cc) {
        int c = z;
        ah = A1h + (long)c * Bsz * Hd;      al = A1l + (long)c * Bsz * Hd;
        wh = W1h + (long)c * G3H * Hd;      wl = W1l + (long)c * G3H * Hd;
        bias = b1 + (long)c * G3H;          Y = Y1 + (long)c * Bsz * G3H;
    } else {
        int c = z - Cc;
        ah = A2h + (long)c * Bsz * Hd;      al = A2l + (long)c * Bsz * Hd;
        wh = W2h + (long)c * G3H * Hd;      wl = W2l + (long)c * G3H * Hd;
        bias = b2 + (long)c * G3H;          Y = Y2 + (long)c * Bsz * G3H;
    }
    gemm_body(smem, ah + (long)b0 * 128, al + (long)b0 * 128,
              wh + (long)g0 * 128, wl + (long)g0 * 128,
              bias, Y, G3H, b0, g0);
}

// ---------------- embedding gather -> bf16 hi/lo split -----------------------
__global__ void gather_x0(const int* __restrict__ tok, const float* __restrict__ emb)
{
    long t = (long)blockIdx.x * 256 + threadIdx.x;   // B*32 threads
    int b  = (int)(t >> 5);
    int e4 = (int)(t & 31) << 2;
    float4 v = *(const float4*)(emb + (long)tok[b] * 128 + e4);
    store_split4(g_x0h, g_x0l, (long)b * 128 + e4, v);
}

// ---------------- GRU elementwise: writes bf16 split only -------------------
// l0bias != nullptr => layer 0: for cells c>0, gi is pure bias (read directly).
__global__ void gru_kernel(const float* __restrict__ hprev,
                           const float* __restrict__ l0bias)
{
    long t   = (long)blockIdx.x * 256 + threadIdx.x;
    long row = t >> 5;
    int  h4  = (int)(t & 31) << 2;
    int  c   = (int)(row >> 14);      // row / Bsz

    const float* gi;
    if (l0bias != nullptr && c > 0)
        gi = l0bias + (long)c * G3H;          // bias broadcast, no gi buffer
    else
        gi = g_gi + row * G3H;
    const float* gh = g_gh + row * G3H;

    float4 ir  = *(const float4*)(gi + h4);
    float4 iz  = *(const float4*)(gi + 128 + h4);
    float4 inn = *(const float4*)(gi + 256 + h4);
    float4 hr  = *(const float4*)(gh + h4);
    float4 hz  = *(const float4*)(gh + 128 + h4);
    float4 hnn = *(const float4*)(gh + 256 + h4);
    float4 hp  = *(const float4*)(hprev + row * 128 + h4);

    float4 out;
    {
        float r = sigf(ir.x + hr.x), z = sigf(iz.x + hz.x);
        float n = tanhf(inn.x + r * hnn.x);
        out.x = (1.0f - z) * n + z * hp.x;
    }
    {
        float r = sigf(ir.y + hr.y), z = sigf(iz.y + hz.y);
        float n = tanhf(inn.y + r * hnn.y);
        out.y = (1.0f - z) * n + z * hp.y;
    }
    {
        float r = sigf(ir.z + hr.z), z = sigf(iz.z + hz.z);
        float n = tanhf(inn.z + r * hnn.z);
        out.z = (1.0f - z) * n + z * hp.z;
    }
    {
        float r = sigf(ir.w + hr.w), z = sigf(iz.w + hz.w);
        float n = tanhf(inn.w + r * hnn.w);
        out.w = (1.0f - z) * n + z * hp.w;
    }
    store_split4(g_nh, g_nl, row * 128 + h4, out);
}

// ---------------- tiny attention over C=4 positions -> bf16 split ------------
__global__ void attn_kernel()
{
    int gw   = blockIdx.x * 4 + (threadIdx.x >> 5);
    int lane = threadIdx.x & 31;
    int b  = gw >> 2;
    int nh = gw & 3;

    float q[4], k[4], v[4];
    #pragma unroll
    for (int c = 0; c < 4; c++) {
        const float* p = g_qkv + ((long)c * Bsz + b) * G3H + nh * 32 + lane;
        q[c] = p[0];
        k[c] = p[128];
        v[c] = p[256];
    }

    float s[4][4];
    #pragma unroll
    for (int qc = 0; qc < 4; qc++) {
        #pragma unroll
        for (int kc = 0; kc < 4; kc++) {
            float p = q[qc] * k[kc];
            #pragma unroll
            for (int off = 16; off > 0; off >>= 1)
                p += __shfl_xor_sync(0xFFFFFFFFu, p, off);
            s[qc][kc] = p * 0.17677669529663687f;   // 1/sqrt(32)
        }
    }

    #pragma unroll
    for (int qc = 0; qc < 4; qc++) {
        float m = fmaxf(fmaxf(s[qc][0], s[qc][1]), fmaxf(s[qc][2], s[qc][3]));
        float e0 = expf(s[qc][0] - m), e1 = expf(s[qc][1] - m);
        float e2 = expf(s[qc][2] - m), e3 = expf(s[qc][3] - m);
        float inv = 1.0f / (e0 + e1 + e2 + e3);
        float o = (e0 * v[0] + e1 * v[1] + e2 * v[2] + e3 * v[3]) * inv;
        long off = ((long)qc * Bsz + b) * 128 + nh * 32 + lane;
        __nv_bfloat16 h = __float2bfloat16(o);
        g_aah[off] = h;
        g_aal[off] = __float2bfloat16(o - __bfloat162float(h));
    }
}

// ---------------- fused LayerNorm + gate + blend -----------------------------
// hn is reconstructed from the bf16 hi/lo split (g_nh + g_nl).
__global__ void lngate_kernel(const float* __restrict__ gg, const float* __restrict__ bb,
                              const float* __restrict__ gw, const float* __restrict__ gbp,
                              float* __restrict__ hout)
{
    int row  = blockIdx.x * 4 + (threadIdx.x >> 5);
    int lane = threadIdx.x & 31;
    const float* mp = g_msg + (long)row * 128;
    long hoff = (long)row * 128 + lane * 4;

    float4 x = *(const float4*)(mp + lane * 4);
    float s = x.x + x.y + x.z + x.w;
    #pragma unroll
    for (int off = 16; off > 0; off >>= 1) s += __shfl_xor_sync(0xFFFFFFFFu, s, off);
    float mean = s * (1.0f / 128.0f);

    float dx = x.x - mean, dy = x.y - mean, dz = x.z - mean, dw = x.w - mean;
    float sq = dx * dx + dy * dy + dz * dz + dw * dw;
    #pragma unroll
    for (int off = 16; off > 0; off >>= 1) sq += __shfl_xor_sync(0xFFFFFFFFu, sq, off);
    float rstd = rsqrtf(sq * (1.0f / 128.0f) + 1e-5f);

    float4 gv = *(const float4*)(gg + lane * 4);
    float4 bv = *(const float4*)(bb + lane * 4);
    float4 m;
    m.x = dx * rstd * gv.x + bv.x;
    m.y = dy * rstd * gv.y + bv.y;
    m.z = dz * rstd * gv.z + bv.z;
    m.w = dw * rstd * gv.w + bv.w;

    float4 hv = load_split4(g_nh, g_nl, hoff);
    float4 w1 = *(const float4*)(gw + lane * 4);
    float4 w2 = *(const float4*)(gw + 128 + lane * 4);

    float p = hv.x * w1.x + hv.y * w1.y + hv.z * w1.z + hv.w * w1.w
            + m.x * w2.x + m.y * w2.y + m.z * w2.z + m.w * w2.w;
    #pragma unroll
    for (int off = 16; off > 0; off >>= 1) p += __shfl_xor_sync(0xFFFFFFFFu, p, off);
    float gt = sigf(p + gbp[0]);

    float4 o;
    o.x = (1.0f - gt) * hv.x + gt * m.x;
    o.y = (1.0f - gt) * hv.y + gt * m.y;
    o.z = (1.0f - gt) * hv.z + gt * m.z;
    o.w = (1.0f - gt) * hv.w + gt * m.w;
    *(float4*)(hout + hoff) = o;
    store_split4(g_ph, g_pl, hoff, o);
}

// ---------------- host orchestration ----------------------------------------
extern "C" void kernel_launch(void* const* d_in, const int* in_sizes, int n_in,
                              void* d_out, int out_size)
{
    const int*   tokens     = (const int*)  d_in[0];
    const float* h_in       = (const float*)d_in[1];
    const float* emb        = (const float*)d_in[2];
    const float* wih0_c0    = (const float*)d_in[3];
    const float* bih0       = (const float*)d_in[5];
    const float* whh0       = (const float*)d_in[6];
    const float* bhh0       = (const float*)d_in[7];
    const float* wih        = (const float*)d_in[8];
    const float* whh        = (const float*)d_in[9];
    const float* bih        = (const float*)d_in[10];
    const float* bhh        = (const float*)d_in[11];
    const float* attn_in_w  = (const float*)d_in[12];
    const float* attn_in_b  = (const float*)d_in[13];
    const float* attn_out_w = (const float*)d_in[14];
    const float* attn_out_b = (const float*)d_in[15];
    const float* ln_g       = (const float*)d_in[16];
    const float* ln_b       = (const float*)d_in[17];
    const float* gate_w     = (const float*)d_in[18];
    const float* gate_b     = (const float*)d_in[19];
    const float* head_w     = (const float*)d_in[20];
    const float* head_b     = (const float*)d_in[21];

    float* yOut = (float*)d_out;                       // (B, O)
    float* hOut = yOut + (size_t)Bsz * Oo;             // (L, C, B, H)

    float *pgi, *pgh, *pqkv, *pmsg;
    cudaGetSymbolAddress((void**)&pgi,  g_gi);
    cudaGetSymbolAddress((void**)&pgh,  g_gh);
    cudaGetSymbolAddress((void**)&pqkv, g_qkv);
    cudaGetSymbolAddress((void**)&pmsg, g_msg);

    __nv_bfloat16 *x0h, *x0l, *hh, *hl, *nh, *nl, *aah, *aal, *ph, *pl;
    __nv_bfloat16 *wih0h, *wih0l, *whh0h, *whh0l, *wihh, *wihl, *whhh, *whhl;
    __nv_bfloat16 *aiwh, *aiwl, *aowh, *aowl, *hwh, *hwl;
    cudaGetSymbolAddress((void**)&x0h, g_x0h);   cudaGetSymbolAddress((void**)&x0l, g_x0l);
    cudaGetSymbolAddress((void**)&hh,  g_hh);    cudaGetSymbolAddress((void**)&hl,  g_hl);
    cudaGetSymbolAddress((void**)&nh,  g_nh);    cudaGetSymbolAddress((void**)&nl,  g_nl);
    cudaGetSymbolAddress((void**)&aah, g_aah);   cudaGetSymbolAddress((void**)&aal, g_aal);
    cudaGetSymbolAddress((void**)&ph,  g_ph);    cudaGetSymbolAddress((void**)&pl,  g_pl);
    cudaGetSymbolAddress((void**)&wih0h, g_wih0h); cudaGetSymbolAddress((void**)&wih0l, g_wih0l);
    cudaGetSymbolAddress((void**)&whh0h, g_whh0h); cudaGetSymbolAddress((void**)&whh0l, g_whh0l);
    cudaGetSymbolAddress((void**)&wihh, g_wihh); cudaGetSymbolAddress((void**)&wihl, g_wihl);
    cudaGetSymbolAddress((void**)&whhh, g_whhh); cudaGetSymbolAddress((void**)&whhl, g_whhl);
    cudaGetSymbolAddress((void**)&aiwh, g_aiwh); cudaGetSymbolAddress((void**)&aiwl, g_aiwl);
    cudaGetSymbolAddress((void**)&aowh, g_aowh); cudaGetSymbolAddress((void**)&aowl, g_aowl);
    cudaGetSymbolAddress((void**)&hwh,  g_hwh);  cudaGetSymbolAddress((void**)&hwl,  g_hwl);

    cudaFuncSetAttribute(gemm_tc,      cudaFuncAttributeMaxDynamicSharedMemorySize, SM_TOT);
    cudaFuncSetAttribute(gemm_tc_dual, cudaFuncAttributeMaxDynamicSharedMemorySize, SM_TOT);

    const long CBH = (long)Cc * Bsz * Hd;
    (void)in_sizes; (void)n_in; (void)out_size;

    // ---- prolog: split weights + h into bf16 hi/lo ----
    #define SPLIT(src, dh, dl, nelem) \
        split_pair<<<(int)((nelem) / 1024), 256>>>(src, dh, dl)
    SPLIT(wih0_c0,   wih0h, wih0l, (long)G3H * Hd);
    SPLIT(whh0,      whh0h, whh0l, (long)Cc * G3H * Hd);
    SPLIT(wih,       wihh,  wihl,  (long)(Ll-1) * Cc * G3H * Hd);
    SPLIT(whh,       whhh,  whhl,  (long)(Ll-1) * Cc * G3H * Hd);
    SPLIT(attn_in_w, aiwh,  aiwl,  (long)Ll * G3H * Hd);
    SPLIT(attn_out_w,aowh,  aowl,  (long)Ll * Hd * Hd);
    SPLIT(head_w,    hwh,   hwl,   (long)Oo * Hd);
    SPLIT(h_in,      hh,    hl,    (long)Ll * CBH);
    #undef SPLIT
    gather_x0<<<(Bsz * 32) / 256, 256>>>(tokens, emb);

    dim3 gB(Bsz / 128, G3H / 64, Cc);
    dim3 gD(Bsz / 128, G3H / 64, 2 * Cc);
    dim3 gO(Bsz / 128, Hd  / 64, Cc);

    for (int l = 0; l < Ll; l++) {
        const float* hlp = h_in + (size_t)l * CBH;

        // ---- gi + gh ----
        if (l == 0) {
            dim3 g1(Bsz / 128, G3H / 64, 1);
            gemm_tc<<<g1, 256, SM_TOT>>>(x0h, x0l, wih0h, wih0l, bih0, pgi,
                                         G3H, 0, 0, 0, 0);
            gemm_tc<<<gB, 256, SM_TOT>>>(hh, hl, whh0h, whh0l, bhh0, pgh, G3H,
                                         (long)Bsz * Hd, (long)G3H * Hd, G3H,
                                         (long)Bsz * G3H);
        } else {
            gemm_tc_dual<<<gD, 256, SM_TOT>>>(
                ph, pl,
                wihh + (size_t)(l - 1) * Cc * G3H * Hd,
                wihl + (size_t)(l - 1) * Cc * G3H * Hd,
                bih + (size_t)(l - 1) * Cc * G3H, pgi,
                hh + (size_t)l * CBH, hl + (size_t)l * CBH,
                whhh + (size_t)(l - 1) * Cc * G3H * Hd,
                whhl + (size_t)(l - 1) * Cc * G3H * Hd,
                bhh + (size_t)(l - 1) * Cc * G3H, pgh);
        }

        // ---- GRU (l=0: cells 1..3 read bias directly, no gi buffer) ----
        gru_kernel<<<((long)Cc * Bsz * 32) / 256, 256>>>(
            hlp, (l == 0) ? bih0 : nullptr);

        // ---- QKV ----
        gemm_tc<<<gB, 256, SM_TOT>>>(nh, nl,
                                     aiwh + (size_t)l * G3H * Hd,
                                     aiwl + (size_t)l * G3H * Hd,
                                     attn_in_b + (size_t)l * G3H,
                                     pqkv, G3H,
                                     (long)Bsz * Hd, 0, 0, (long)Bsz * G3H);

        // ---- attention ----
        attn_kernel<<<(Bsz * NHh) / 4, 128>>>();

        // ---- out projection ----
        gemm_tc<<<gO, 256, SM_TOT>>>(aah, aal,
                                     aowh + (size_t)l * Hd * Hd,
                                     aowl + (size_t)l * Hd * Hd,
                                     attn_out_b + (size_t)l * Hd,
                                     pmsg, Hd,
                                     (long)Bsz * Hd, 0, 0, (long)Bsz * Hd);

        // ---- fused LN + gate + blend -> hOut + g_ph/g_pl split ----
        lngate_kernel<<<(Cc * Bsz) / 4, 128>>>(ln_g + (size_t)l * Hd, ln_b + (size_t)l * Hd,
                                               gate_w + (size_t)l * 2 * Hd, gate_b + l,
                                               hOut + (size_t)l * CBH);
    }

    // ---- head: y = h_n[L-1, 0] @ head_w.T + head_b ----
    dim3 gH(Bsz / 128, Oo / 64, 1);
    gemm_tc<<<gH, 256, SM_TOT>>>(ph, pl, hwh, hwl, head_b, yOut, Oo, 0, 0, 0, 0);
}

// round 16
// speedup vs baseline: 1.1620x; 1.0464x over previous
#include <cuda_runtime.h>
#include <cuda_bf16.h>
#include <math.h>
#include <stdint.h>

#define Bsz 16384
#define Hd  128
#define Cc  4
#define Ll  6
#define NHh 4
#define HDd 32
#define Oo  1024
#define G3H 384

// ---------------- fp32 scratch ----------------------------------------------
__device__ __align__(256) float g_gi [(size_t)Cc * Bsz * G3H];
__device__ __align__(256) float g_gh [(size_t)Cc * Bsz * G3H];
__device__ __align__(256) float g_qkv[(size_t)Cc * Bsz * G3H];
__device__ __align__(256) float g_msg[(size_t)Cc * Bsz * Hd];

// ---------------- bf16 hi/lo split buffers ----------------------------------
__device__ __align__(256) __nv_bfloat16 g_x0h[(size_t)Bsz * Hd];
__device__ __align__(256) __nv_bfloat16 g_x0l[(size_t)Bsz * Hd];
__device__ __align__(256) __nv_bfloat16 g_hh [(size_t)Ll * Cc * Bsz * Hd];  // h_in split
__device__ __align__(256) __nv_bfloat16 g_hl [(size_t)Ll * Cc * Bsz * Hd];
__device__ __align__(256) __nv_bfloat16 g_nh [(size_t)Cc * Bsz * Hd];       // hn split
__device__ __align__(256) __nv_bfloat16 g_nl [(size_t)Cc * Bsz * Hd];
__device__ __align__(256) __nv_bfloat16 g_aah[(size_t)Cc * Bsz * Hd];       // att split
__device__ __align__(256) __nv_bfloat16 g_aal[(size_t)Cc * Bsz * Hd];
__device__ __align__(256) __nv_bfloat16 g_ph [(size_t)Cc * Bsz * Hd];       // hOut split
__device__ __align__(256) __nv_bfloat16 g_pl [(size_t)Cc * Bsz * Hd];
// weights
__device__ __align__(256) __nv_bfloat16 g_wih0h[(size_t)G3H * Hd];
__device__ __align__(256) __nv_bfloat16 g_wih0l[(size_t)G3H * Hd];
__device__ __align__(256) __nv_bfloat16 g_whh0h[(size_t)Cc * G3H * Hd];
__device__ __align__(256) __nv_bfloat16 g_whh0l[(size_t)Cc * G3H * Hd];
__device__ __align__(256) __nv_bfloat16 g_wihh[(size_t)(Ll-1) * Cc * G3H * Hd];
__device__ __align__(256) __nv_bfloat16 g_wihl[(size_t)(Ll-1) * Cc * G3H * Hd];
__device__ __align__(256) __nv_bfloat16 g_whhh[(size_t)(Ll-1) * Cc * G3H * Hd];
__device__ __align__(256) __nv_bfloat16 g_whhl[(size_t)(Ll-1) * Cc * G3H * Hd];
__device__ __align__(256) __nv_bfloat16 g_aiwh[(size_t)Ll * G3H * Hd];
__device__ __align__(256) __nv_bfloat16 g_aiwl[(size_t)Ll * G3H * Hd];
__device__ __align__(256) __nv_bfloat16 g_aowh[(size_t)Ll * Hd * Hd];
__device__ __align__(256) __nv_bfloat16 g_aowl[(size_t)Ll * Hd * Hd];
__device__ __align__(256) __nv_bfloat16 g_hwh [(size_t)Oo * Hd];
__device__ __align__(256) __nv_bfloat16 g_hwl [(size_t)Oo * Hd];

__device__ __forceinline__ float sigf(float x) { return 1.0f / (1.0f + expf(-x)); }

__device__ __forceinline__ uint32_t pack_bf16(__nv_bfloat16 a, __nv_bfloat16 b) {
    __nv_bfloat162 t = __nv_bfloat162(a, b);
    return *reinterpret_cast<uint32_t*>(&t);
}

__device__ __forceinline__ void store_split4(__nv_bfloat16* ph, __nv_bfloat16* pl,
                                             long off, float4 v) {
    __nv_bfloat16 h0 = __float2bfloat16(v.x);
    __nv_bfloat16 h1 = __float2bfloat16(v.y);
    __nv_bfloat16 h2 = __float2bfloat16(v.z);
    __nv_bfloat16 h3 = __float2bfloat16(v.w);
    *reinterpret_cast<uint2*>(ph + off) =
        make_uint2(pack_bf16(h0, h1), pack_bf16(h2, h3));
    __nv_bfloat16 l0 = __float2bfloat16(v.x - __bfloat162float(h0));
    __nv_bfloat16 l1 = __float2bfloat16(v.y - __bfloat162float(h1));
    __nv_bfloat16 l2 = __float2bfloat16(v.z - __bfloat162float(h2));
    __nv_bfloat16 l3 = __float2bfloat16(v.w - __bfloat162float(h3));
    *reinterpret_cast<uint2*>(pl + off) =
        make_uint2(pack_bf16(l0, l1), pack_bf16(l2, l3));
}

// load 4 consecutive split values and reconstruct fp32 (hi + lo)
__device__ __forceinline__ float4 load_split4(const __nv_bfloat16* ph,
                                              const __nv_bfloat16* pl, long off) {
    uint2 uh = *reinterpret_cast<const uint2*>(ph + off);
    uint2 ul = *reinterpret_cast<const uint2*>(pl + off);
    __nv_bfloat162 h01 = *reinterpret_cast<__nv_bfloat162*>(&uh.x);
    __nv_bfloat162 h23 = *reinterpret_cast<__nv_bfloat162*>(&uh.y);
    __nv_bfloat162 l01 = *reinterpret_cast<__nv_bfloat162*>(&ul.x);
    __nv_bfloat162 l23 = *reinterpret_cast<__nv_bfloat162*>(&ul.y);
    float4 v;
    v.x = __bfloat162float(h01.x) + __bfloat162float(l01.x);
    v.y = __bfloat162float(h01.y) + __bfloat162float(l01.y);
    v.z = __bfloat162float(h23.x) + __bfloat162float(l23.x);
    v.w = __bfloat162float(h23.y) + __bfloat162float(l23.y);
    return v;
}

// ---------------- generic fp32 -> bf16 hi/lo split pass ---------------------
__global__ void split_pair(const float* __restrict__ in, __nv_bfloat16* __restrict__ oh,
                           __nv_bfloat16* __restrict__ ol)
{
    long i = (long)blockIdx.x * 256 + threadIdx.x;   // float4 index
    float4 v = reinterpret_cast<const float4*>(in)[i];
    store_split4(oh, ol, i * 4, v);
}

// ======================= HMMA (mma.sync) GEMM =======================
// CTA tile 128(b) x 64(g), 256 threads, 8 warps (4m x 2n), warp tile 32x32,
// 2 CTAs/SM. Term-major MMA ordering; 2-stage pipelined k-split fill.

#define KPAD    136
#define ROWB    (KPAD * 2)            // 272 bytes per row
#define TILE_A  ((size_t)128 * ROWB)
#define TILE_Bt ((size_t)64  * ROWB)
#define SM_AH   0
#define SM_AL   (SM_AH + TILE_A)
#define SM_BH   (SM_AL + TILE_A)
#define SM_BL   (SM_BH + TILE_Bt)
#define SM_TOT  (SM_BL + TILE_Bt)     // 104448 bytes

__device__ __forceinline__ uint32_t smem_u32(const void* p) {
    uint32_t a;
    asm("{ .reg .u64 t; cvta.to.shared.u64 t, %1; cvt.u32.u64 %0, t; }" : "=r"(a) : "l"(p));
    return a;
}
__device__ __forceinline__ void cpa16(uint32_t sdst, const void* gsrc) {
    asm volatile("cp.async.cg.shared.global [%0], [%1], 16;" :: "r"(sdst), "l"(gsrc));
}
#define CP_COMMIT() asm volatile("cp.async.commit_group;" ::: "memory")
#define CP_WAIT(n)  asm volatile("cp.async.wait_group %0;" :: "n"(n) : "memory")

__device__ __forceinline__ void mma16816(float* c, const uint32_t* a, const uint32_t* b) {
    asm volatile(
        "mma.sync.aligned.m16n8k16.row.col.f32.bf16.bf16.f32 "
        "{%0,%1,%2,%3}, {%4,%5,%6,%7}, {%8,%9}, {%0,%1,%2,%3};\n"
        : "+f"(c[0]), "+f"(c[1]), "+f"(c[2]), "+f"(c[3])
        : "r"(a[0]), "r"(a[1]), "r"(a[2]), "r"(a[3]), "r"(b[0]), "r"(b[1]));
}

#define LDSM_X4(r0, r1, r2, r3, addr) \
    asm volatile("ldmatrix.sync.aligned.m8n8.x4.shared.b16 {%0,%1,%2,%3}, [%4];" \
                 : "=r"(r0), "=r"(r1), "=r"(r2), "=r"(r3) : "r"(addr))

struct Frags {
    uint32_t ah[2][4];
    uint32_t al[2][4];
    uint32_t bh[4][2];
    uint32_t bl[4][2];
};

__device__ __forceinline__ void ld_frags(Frags& f, uint32_t aH, uint32_t aL,
                                         uint32_t bH, uint32_t bL) {
    #pragma unroll
    for (int i = 0; i < 2; i++)
        LDSM_X4(f.ah[i][0], f.ah[i][1], f.ah[i][2], f.ah[i][3], aH + i * (16 * ROWB));
    #pragma unroll
    for (int i = 0; i < 2; i++)
        LDSM_X4(f.al[i][0], f.al[i][1], f.al[i][2], f.al[i][3], aL + i * (16 * ROWB));
    LDSM_X4(f.bh[0][0], f.bh[0][1], f.bh[1][0], f.bh[1][1], bH);
    LDSM_X4(f.bh[2][0], f.bh[2][1], f.bh[3][0], f.bh[3][1], bH + 16 * ROWB);
    LDSM_X4(f.bl[0][0], f.bl[0][1], f.bl[1][0], f.bl[1][1], bL);
    LDSM_X4(f.bl[2][0], f.bl[2][1], f.bl[3][0], f.bl[3][1], bL + 16 * ROWB);
}

__device__ __forceinline__ void mma_all(float acc[2][4][4], Frags& f) {
    // term-major: 8 independent MMAs between accumulator reuses
    #pragma unroll
    for (int i = 0; i < 2; i++)
        #pragma unroll
        for (int j = 0; j < 4; j++)
            mma16816(acc[i][j], f.ah[i], f.bh[j]);
    #pragma unroll
    for (int i = 0; i < 2; i++)
        #pragma unroll
        for (int j = 0; j < 4; j++)
            mma16816(acc[i][j], f.ah[i], f.bl[j]);
    #pragma unroll
    for (int i = 0; i < 2; i++)
        #pragma unroll
        for (int j = 0; j < 4; j++)
            mma16816(acc[i][j], f.al[i], f.bh[j]);
}

// fill one k-half (chunks [h*8, h*8+8) of 16B per row) for A and B tiles
__device__ __forceinline__ void fill_half(
    uint32_t sb, int tid, int h,
    const __nv_bfloat16* a_h, const __nv_bfloat16* a_l,
    const __nv_bfloat16* b_h, const __nv_bfloat16* b_l)
{
    #pragma unroll 2
    for (int idx = tid; idx < 1024; idx += 256) {        // A: 128 rows x 8 chunks
        int r = idx >> 3, k = (idx & 7) + h * 8;
        cpa16(sb + SM_AH + r * ROWB + k * 16, a_h + (long)r * 128 + k * 8);
        cpa16(sb + SM_AL + r * ROWB + k * 16, a_l + (long)r * 128 + k * 8);
    }
    #pragma unroll 2
    for (int idx = tid; idx < 512; idx += 256) {         // B: 64 rows x 8 chunks
        int r = idx >> 3, k = (idx & 7) + h * 8;
        cpa16(sb + SM_BH + r * ROWB + k * 16, b_h + (long)r * 128 + k * 8);
        cpa16(sb + SM_BL + r * ROWB + k * 16, b_l + (long)r * 128 + k * 8);
    }
}

// shared GEMM body: 2-stage pipelined fill, term-major mainloop, epilogue
__device__ __forceinline__ void gemm_body(
    char* smem,
    const __nv_bfloat16* __restrict__ a_h, const __nv_bfloat16* __restrict__ a_l,
    const __nv_bfloat16* __restrict__ b_h, const __nv_bfloat16* __restrict__ b_l,
    const float* __restrict__ bias, float* __restrict__ Y,
    int G, int b0, int g0)
{
    int tid  = threadIdx.x;
    int wid  = tid >> 5;
    int lane = tid & 31;
    uint32_t sb = smem_u32(smem);

    fill_half(sb, tid, 0, a_h, a_l, b_h, b_l);
    CP_COMMIT();
    fill_half(sb, tid, 1, a_h, a_l, b_h, b_l);
    CP_COMMIT();

    int wm = (wid & 3) * 32;
    int wn = (wid >> 2) * 32;

    int a_lane = (wm + (lane & 7) + ((lane >> 3) & 1) * 8) * ROWB + (lane >> 4) * 16;
    int b_lane = (wn + (lane & 7) + ((lane >> 4) & 1) * 8) * ROWB + ((lane >> 3) & 1) * 16;

    uint32_t aH = sb + SM_AH + a_lane;
    uint32_t aL = sb + SM_AL + a_lane;
    uint32_t bH = sb + SM_BH + b_lane;
    uint32_t bL = sb + SM_BL + b_lane;

    float acc[2][4][4];
    #pragma unroll
    for (int i = 0; i < 2; i++)
        #pragma unroll
        for (int j = 0; j < 4; j++)
            #pragma unroll
            for (int r = 0; r < 4; r++) acc[i][j][r] = 0.0f;

    Frags fr[2];

    // ---- first k-half (steps 0..3) ----
    CP_WAIT(1);
    __syncthreads();
    ld_frags(fr[0], aH, aL, bH, bL);
    #pragma unroll
    for (int kk = 0; kk < 4; kk++) {
        if (kk < 3) {
            int ko = (kk + 1) * 32;
            ld_frags(fr[(kk + 1) & 1], aH + ko, aL + ko, bH + ko, bL + ko);
        }
        mma_all(acc, fr[kk & 1]);
    }

    // ---- second k-half (steps 4..7) ----
    CP_WAIT(0);
    __syncthreads();
    ld_frags(fr[0], aH + 128, aL + 128, bH + 128, bL + 128);
    #pragma unroll
    for (int kk = 0; kk < 4; kk++) {
        if (kk < 3) {
            int ko = 128 + (kk + 1) * 32;
            ld_frags(fr[(kk + 1) & 1], aH + ko, aL + ko, bH + ko, bL + ko);
        }
        mma_all(acc, fr[kk & 1]);
    }

    int colb = g0 + wn + (lane & 3) * 2;
    #pragma unroll
    for (int i = 0; i < 2; i++) {
        int row = b0 + wm + i * 16 + (lane >> 2);
        #pragma unroll
        for (int j = 0; j < 4; j++) {
            int col = colb + j * 8;
            float bx = bias[col], by = bias[col + 1];
            float2 o0 = make_float2(acc[i][j][0] + bx, acc[i][j][1] + by);
            float2 o1 = make_float2(acc[i][j][2] + bx, acc[i][j][3] + by);
            *reinterpret_cast<float2*>(Y + (long)row * G + col)       = o0;
            *reinterpret_cast<float2*>(Y + (long)(row + 8) * G + col) = o1;
        }
    }
}

__global__ __launch_bounds__(256, 2) void gemm_tc(
    const __nv_bfloat16* __restrict__ Ah, const __nv_bfloat16* __restrict__ Al,
    const __nv_bfloat16* __restrict__ Bh, const __nv_bfloat16* __restrict__ Bl,
    const float* __restrict__ bias, float* __restrict__ Y,
    int G, long xStride, long wStride, long bStride, long yStride)
{
    extern __shared__ char smem[];
    int c = blockIdx.z;
    int b0 = blockIdx.x * 128;
    int g0 = blockIdx.y * 64;
    gemm_body(smem,
              Ah + (long)c * xStride + (long)b0 * 128,
              Al + (long)c * xStride + (long)b0 * 128,
              Bh + (long)c * wStride + (long)g0 * 128,
              Bl + (long)c * wStride + (long)g0 * 128,
              bias + (long)c * bStride,
              Y + (long)c * yStride, G, b0, g0);
}

// dual-set GEMM: z in [0, 2*Cc); z<Cc -> set1 (gi), else set2 (gh).
__global__ __launch_bounds__(256, 2) void gemm_tc_dual(
    const __nv_bfloat16* __restrict__ A1h, const __nv_bfloat16* __restrict__ A1l,
    const __nv_bfloat16* __restrict__ W1h, const __nv_bfloat16* __restrict__ W1l,
    const float* __restrict__ b1, float* __restrict__ Y1,
    const __nv_bfloat16* __restrict__ A2h, const __nv_bfloat16* __restrict__ A2l,
    const __nv_bfloat16* __restrict__ W2h, const __nv_bfloat16* __restrict__ W2l,
    const float* __restrict__ b2, float* __restrict__ Y2)
{
    extern __shared__ char smem[];
    int z  = blockIdx.z;
    int b0 = blockIdx.x * 128;
    int g0 = blockIdx.y * 64;
    const __nv_bfloat16 *ah, *al, *wh, *wl;
    const float* bias;
    float* Y;
    if (z < Cc) {
        int c = z;
        ah = A1h + (long)c * Bsz * Hd;      al = A1l + (long)c * Bsz * Hd;
        wh = W1h + (long)c * G3H * Hd;      wl = W1l + (long)c * G3H * Hd;
        bias = b1 + (long)c * G3H;          Y = Y1 + (long)c * Bsz * G3H;
    } else {
        int c = z - Cc;
        ah = A2h + (long)c * Bsz * Hd;      al = A2l + (long)c * Bsz * Hd;
        wh = W2h + (long)c * G3H * Hd;      wl = W2l + (long)c * G3H * Hd;
        bias = b2 + (long)c * G3H;          Y = Y2 + (long)c * Bsz * G3H;
    }
    gemm_body(smem, ah + (long)b0 * 128, al + (long)b0 * 128,
              wh + (long)g0 * 128, wl + (long)g0 * 128,
              bias, Y, G3H, b0, g0);
}

// ---------------- embedding gather -> bf16 hi/lo split -----------------------
__global__ void gather_x0(const int* __restrict__ tok, const float* __restrict__ emb)
{
    long t = (long)blockIdx.x * 256 + threadIdx.x;   // B*32 threads
    int b  = (int)(t >> 5);
    int e4 = (int)(t & 31) << 2;
    float4 v = *(const float4*)(emb + (long)tok[b] * 128 + e4);
    store_split4(g_x0h, g_x0l, (long)b * 128 + e4, v);
}

// ---------------- GRU elementwise: writes bf16 split only -------------------
// l0bias != nullptr => layer 0: for cells c>0, gi is pure bias (read directly).
__global__ void gru_kernel(const float* __restrict__ hprev,
                           const float* __restrict__ l0bias)
{
    long t   = (long)blockIdx.x * 256 + threadIdx.x;
    long row = t >> 5;
    int  h4  = (int)(t & 31) << 2;
    int  c   = (int)(row >> 14);      // row / Bsz

    const float* gi;
    if (l0bias != nullptr && c > 0)
        gi = l0bias + (long)c * G3H;          // bias broadcast, no gi buffer
    else
        gi = g_gi + row * G3H;
    const float* gh = g_gh + row * G3H;

    float4 ir  = *(const float4*)(gi + h4);
    float4 iz  = *(const float4*)(gi + 128 + h4);
    float4 inn = *(const float4*)(gi + 256 + h4);
    float4 hr  = *(const float4*)(gh + h4);
    float4 hz  = *(const float4*)(gh + 128 + h4);
    float4 hnn = *(const float4*)(gh + 256 + h4);
    float4 hp  = *(const float4*)(hprev + row * 128 + h4);

    float4 out;
    {
        float r = sigf(ir.x + hr.x), z = sigf(iz.x + hz.x);
        float n = tanhf(inn.x + r * hnn.x);
        out.x = (1.0f - z) * n + z * hp.x;
    }
    {
        float r = sigf(ir.y + hr.y), z = sigf(iz.y + hz.y);
        float n = tanhf(inn.y + r * hnn.y);
        out.y = (1.0f - z) * n + z * hp.y;
    }
    {
        float r = sigf(ir.z + hr.z), z = sigf(iz.z + hz.z);
        float n = tanhf(inn.z + r * hnn.z);
        out.z = (1.0f - z) * n + z * hp.z;
    }
    {
        float r = sigf(ir.w + hr.w), z = sigf(iz.w + hz.w);
        float n = tanhf(inn.w + r * hnn.w);
        out.w = (1.0f - z) * n + z * hp.w;
    }
    store_split4(g_nh, g_nl, row * 128 + h4, out);
}

// ---------------- tiny attention over C=4 positions -> bf16 split ------------
__global__ void attn_kernel()
{
    int gw   = blockIdx.x * 4 + (threadIdx.x >> 5);
    int lane = threadIdx.x & 31;
    int b  = gw >> 2;
    int nh = gw & 3;

    float q[4], k[4], v[4];
    #pragma unroll
    for (int c = 0; c < 4; c++) {
        const float* p = g_qkv + ((long)c * Bsz + b) * G3H + nh * 32 + lane;
        q[c] = p[0];
        k[c] = p[128];
        v[c] = p[256];
    }

    float s[4][4];
    #pragma unroll
    for (int qc = 0; qc < 4; qc++) {
        #pragma unroll
        for (int kc = 0; kc < 4; kc++) {
            float p = q[qc] * k[kc];
            #pragma unroll
            for (int off = 16; off > 0; off >>= 1)
                p += __shfl_xor_sync(0xFFFFFFFFu, p, off);
            s[qc][kc] = p * 0.17677669529663687f;   // 1/sqrt(32)
        }
    }

    #pragma unroll
    for (int qc = 0; qc < 4; qc++) {
        float m = fmaxf(fmaxf(s[qc][0], s[qc][1]), fmaxf(s[qc][2], s[qc][3]));
        float e0 = expf(s[qc][0] - m), e1 = expf(s[qc][1] - m);
        float e2 = expf(s[qc][2] - m), e3 = expf(s[qc][3] - m);
        float inv = 1.0f / (e0 + e1 + e2 + e3);
        float o = (e0 * v[0] + e1 * v[1] + e2 * v[2] + e3 * v[3]) * inv;
        long off = ((long)qc * Bsz + b) * 128 + nh * 32 + lane;
        __nv_bfloat16 h = __float2bfloat16(o);
        g_aah[off] = h;
        g_aal[off] = __float2bfloat16(o - __bfloat162float(h));
    }
}

// ---------------- fused LayerNorm + gate + blend -----------------------------
// hn is reconstructed from the bf16 hi/lo split (g_nh + g_nl).
__global__ void lngate_kernel(const float* __restrict__ gg, const float* __restrict__ bb,
                              const float* __restrict__ gw, const float* __restrict__ gbp,
                              float* __restrict__ hout)
{
    int row  = blockIdx.x * 4 + (threadIdx.x >> 5);
    int lane = threadIdx.x & 31;
    const float* mp = g_msg + (long)row * 128;
    long hoff = (long)row * 128 + lane * 4;

    float4 x = *(const float4*)(mp + lane * 4);
    float s = x.x + x.y + x.z + x.w;
    #pragma unroll
    for (int off = 16; off > 0; off >>= 1) s += __shfl_xor_sync(0xFFFFFFFFu, s, off);
    float mean = s * (1.0f / 128.0f);

    float dx = x.x - mean, dy = x.y - mean, dz = x.z - mean, dw = x.w - mean;
    float sq = dx * dx + dy * dy + dz * dz + dw * dw;
    #pragma unroll
    for (int off = 16; off > 0; off >>= 1) sq += __shfl_xor_sync(0xFFFFFFFFu, sq, off);
    float rstd = rsqrtf(sq * (1.0f / 128.0f) + 1e-5f);

    float4 gv = *(const float4*)(gg + lane * 4);
    float4 bv = *(const float4*)(bb + lane * 4);
    float4 m;
    m.x = dx * rstd * gv.x + bv.x;
    m.y = dy * rstd * gv.y + bv.y;
    m.z = dz * rstd * gv.z + bv.z;
    m.w = dw * rstd * gv.w + bv.w;

    float4 hv = load_split4(g_nh, g_nl, hoff);
    float4 w1 = *(const float4*)(gw + lane * 4);
    float4 w2 = *(const float4*)(gw + 128 + lane * 4);

    float p = hv.x * w1.x + hv.y * w1.y + hv.z * w1.z + hv.w * w1.w
            + m.x * w2.x + m.y * w2.y + m.z * w2.z + m.w * w2.w;
    #pragma unroll
    for (int off = 16; off > 0; off >>= 1) p += __shfl_xor_sync(0xFFFFFFFFu, p, off);
    float gt = sigf(p + gbp[0]);

    float4 o;
    o.x = (1.0f - gt) * hv.x + gt * m.x;
    o.y = (1.0f - gt) * hv.y + gt * m.y;
    o.z = (1.0f - gt) * hv.z + gt * m.z;
    o.w = (1.0f - gt) * hv.w + gt * m.w;
    *(float4*)(hout + hoff) = o;
    store_split4(g_ph, g_pl, hoff, o);
}

// ---------------- host orchestration ----------------------------------------
extern "C" void kernel_launch(void* const* d_in, const int* in_sizes, int n_in,
                              void* d_out, int out_size)
{
    const int*   tokens     = (const int*)  d_in[0];
    const float* h_in       = (const float*)d_in[1];
    const float* emb        = (const float*)d_in[2];
    const float* wih0_c0    = (const float*)d_in[3];
    const float* bih0       = (const float*)d_in[5];
    const float* whh0       = (const float*)d_in[6];
    const float* bhh0       = (const float*)d_in[7];
    const float* wih        = (const float*)d_in[8];
    const float* whh        = (const float*)d_in[9];
    const float* bih        = (const float*)d_in[10];
    const float* bhh        = (const float*)d_in[11];
    const float* attn_in_w  = (const float*)d_in[12];
    const float* attn_in_b  = (const float*)d_in[13];
    const float* attn_out_w = (const float*)d_in[14];
    const float* attn_out_b = (const float*)d_in[15];
    const float* ln_g       = (const float*)d_in[16];
    const float* ln_b       = (const float*)d_in[17];
    const float* gate_w     = (const float*)d_in[18];
    const float* gate_b     = (const float*)d_in[19];
    const float* head_w     = (const float*)d_in[20];
    const float* head_b     = (const float*)d_in[21];

    float* yOut = (float*)d_out;                       // (B, O)
    float* hOut = yOut + (size_t)Bsz * Oo;             // (L, C, B, H)

    float *pgi, *pgh, *pqkv, *pmsg;
    cudaGetSymbolAddress((void**)&pgi,  g_gi);
    cudaGetSymbolAddress((void**)&pgh,  g_gh);
    cudaGetSymbolAddress((void**)&pqkv, g_qkv);
    cudaGetSymbolAddress((void**)&pmsg, g_msg);

    __nv_bfloat16 *x0h, *x0l, *hh, *hl, *nh, *nl, *aah, *aal, *ph, *pl;
    __nv_bfloat16 *wih0h, *wih0l, *whh0h, *whh0l, *wihh, *wihl, *whhh, *whhl;
    __nv_bfloat16 *aiwh, *aiwl, *aowh, *aowl, *hwh, *hwl;
    cudaGetSymbolAddress((void**)&x0h, g_x0h);   cudaGetSymbolAddress((void**)&x0l, g_x0l);
    cudaGetSymbolAddress((void**)&hh,  g_hh);    cudaGetSymbolAddress((void**)&hl,  g_hl);
    cudaGetSymbolAddress((void**)&nh,  g_nh);    cudaGetSymbolAddress((void**)&nl,  g_nl);
    cudaGetSymbolAddress((void**)&aah, g_aah);   cudaGetSymbolAddress((void**)&aal, g_aal);
    cudaGetSymbolAddress((void**)&ph,  g_ph);    cudaGetSymbolAddress((void**)&pl,  g_pl);
    cudaGetSymbolAddress((void**)&wih0h, g_wih0h); cudaGetSymbolAddress((void**)&wih0l, g_wih0l);
    cudaGetSymbolAddress((void**)&whh0h, g_whh0h); cudaGetSymbolAddress((void**)&whh0l, g_whh0l);
    cudaGetSymbolAddress((void**)&wihh, g_wihh); cudaGetSymbolAddress((void**)&wihl, g_wihl);
    cudaGetSymbolAddress((void**)&whhh, g_whhh); cudaGetSymbolAddress((void**)&whhl, g_whhl);
    cudaGetSymbolAddress((void**)&aiwh, g_aiwh); cudaGetSymbolAddress((void**)&aiwl, g_aiwl);
    cudaGetSymbolAddress((void**)&aowh, g_aowh); cudaGetSymbolAddress((void**)&aowl, g_aowl);
    cudaGetSymbolAddress((void**)&hwh,  g_hwh);  cudaGetSymbolAddress((void**)&hwl,  g_hwl);

    cudaFuncSetAttribute(gemm_tc,      cudaFuncAttributeMaxDynamicSharedMemorySize, SM_TOT);
    cudaFuncSetAttribute(gemm_tc_dual, cudaFuncAttributeMaxDynamicSharedMemorySize, SM_TOT);

    const long CBH = (long)Cc * Bsz * Hd;
    (void)in_sizes; (void)n_in; (void)out_size;

    // ---- prolog: split weights + h into bf16 hi/lo ----
    #define SPLIT(src, dh, dl, nelem) \
        split_pair<<<(int)((nelem) / 1024), 256>>>(src, dh, dl)
    SPLIT(wih0_c0,   wih0h, wih0l, (long)G3H * Hd);
    SPLIT(whh0,      whh0h, whh0l, (long)Cc * G3H * Hd);
    SPLIT(wih,       wihh,  wihl,  (long)(Ll-1) * Cc * G3H * Hd);
    SPLIT(whh,       whhh,  whhl,  (long)(Ll-1) * Cc * G3H * Hd);
    SPLIT(attn_in_w, aiwh,  aiwl,  (long)Ll * G3H * Hd);
    SPLIT(attn_out_w,aowh,  aowl,  (long)Ll * Hd * Hd);
    SPLIT(head_w,    hwh,   hwl,   (long)Oo * Hd);
    SPLIT(h_in,      hh,    hl,    (long)Ll * CBH);
    #undef SPLIT
    gather_x0<<<(Bsz * 32) / 256, 256>>>(tokens, emb);

    dim3 gB(Bsz / 128, G3H / 64, Cc);
    dim3 gD(Bsz / 128, G3H / 64, 2 * Cc);
    dim3 gO(Bsz / 128, Hd  / 64, Cc);

    for (int l = 0; l < Ll; l++) {
        const float* hlp = h_in + (size_t)l * CBH;

        // ---- gi + gh ----
        if (l == 0) {
            dim3 g1(Bsz / 128, G3H / 64, 1);
            gemm_tc<<<g1, 256, SM_TOT>>>(x0h, x0l, wih0h, wih0l, bih0, pgi,
                                         G3H, 0, 0, 0, 0);
            gemm_tc<<<gB, 256, SM_TOT>>>(hh, hl, whh0h, whh0l, bhh0, pgh, G3H,
                                         (long)Bsz * Hd, (long)G3H * Hd, G3H,
                                         (long)Bsz * G3H);
        } else {
            gemm_tc_dual<<<gD, 256, SM_TOT>>>(
                ph, pl,
                wihh + (size_t)(l - 1) * Cc * G3H * Hd,
                wihl + (size_t)(l - 1) * Cc * G3H * Hd,
                bih + (size_t)(l - 1) * Cc * G3H, pgi,
                hh + (size_t)l * CBH, hl + (size_t)l * CBH,
                whhh + (size_t)(l - 1) * Cc * G3H * Hd,
                whhl + (size_t)(l - 1) * Cc * G3H * Hd,
                bhh + (size_t)(l - 1) * Cc * G3H, pgh);
        }

        // ---- GRU (l=0: cells 1..3 read bias directly, no gi buffer) ----
        gru_kernel<<<((long)Cc * Bsz * 32) / 256, 256>>>(
            hlp, (l == 0) ? bih0 : nullptr);

        // ---- QKV ----
        gemm_tc<<<gB, 256, SM_TOT>>>(nh, nl,
                                     aiwh + (size_t)l * G3H * Hd,
                                     aiwl + (size_t)l * G3H * Hd,
                                     attn_in_b + (size_t)l * G3H,
                                     pqkv, G3H,
                                     (long)Bsz * Hd, 0, 0, (long)Bsz * G3H);

        // ---- attention ----
        attn_kernel<<<(Bsz * NHh) / 4, 128>>>();

        // ---- out projection ----
        gemm_tc<<<gO, 256, SM_TOT>>>(aah, aal,
                                     aowh + (size_t)l * Hd * Hd,
                                     aowl + (size_t)l * Hd * Hd,
                                     attn_out_b + (size_t)l * Hd,
                                     pmsg, Hd,
                                     (long)Bsz * Hd, 0, 0, (long)Bsz * Hd);

        // ---- fused LN + gate + blend -> hOut + g_ph/g_pl split ----
        lngate_kernel<<<(Cc * Bsz) / 4, 128>>>(ln_g + (size_t)l * Hd, ln_b + (size_t)l * Hd,
                                               gate_w + (size_t)l * 2 * Hd, gate_b + l,
                                               hOut + (size_t)l * CBH);
    }

    // ---- head: y = h_n[L-1, 0] @ head_w.T + head_b ----
    dim3 gH(Bsz / 128, Oo / 64, 1);
    gemm_tc<<<gH, 256, SM_TOT>>>(ph, pl, hwh, hwl, head_b, yOut, Oo, 0, 0, 0, 0);
}